// round 13
// baseline (speedup 1.0000x reference)
#include <cuda_runtime.h>
#include <math.h>

typedef unsigned long long u64;

// ---------------- f32x2 packed helpers ----------------
__device__ __forceinline__ u64 fma2(u64 a, u64 b, u64 c) {
    u64 d; asm("fma.rn.f32x2 %0, %1, %2, %3;" : "=l"(d) : "l"(a), "l"(b), "l"(c)); return d;
}
__device__ __forceinline__ u64 pack2(float x, float y) {
    u64 r; asm("mov.b64 %0, {%1, %2};" : "=l"(r) : "f"(x), "f"(y)); return r;
}
__device__ __forceinline__ float hsum2(u64 v) {
    float a, b; asm("mov.b64 {%0, %1}, %2;" : "=f"(a), "=f"(b) : "l"(v)); return a + b;
}
__device__ __forceinline__ void unpack2(u64 v, float& a, float& b) {
    asm("mov.b64 {%0, %1}, %2;" : "=f"(a), "=f"(b) : "l"(v));
}
union F4U { float4 f; u64 u[2]; };
__device__ __forceinline__ void ld2x(const float* p, u64& a, u64& b) {
    F4U t; t.f = *(const float4*)p; a = t.u[0]; b = t.u[1];
}

// ---------------- scratch (no allocs allowed) ----------------
__device__ float g_ho[52428800];    // (b,h,d,t)  210 MB
__device__ float g_z1[104857600];   // (b,h,f,t)  419 MB
__device__ float g_z2[52428800];    // (b,h,g,t)  210 MB
__device__ float g_qkv[39321600];   // (b,h,t,48) 157 MB  [q|k|v 16 each]
__device__ float g_c1[524288];      // (b,h,f)    2 MB
__device__ float g_w2t[16384];      // transposed ffn_w2 [h][f][j]
__device__ double g_p1[4096 * 2];
__device__ double g_p2[2048 * 2];
__device__ float g_mean1[512], g_istd1[512];
__device__ float g_mean2[256], g_istd2[256];

// ---------------- kernel W: one-shot transpose of ffn_w2 ----------------
__global__ void __launch_bounds__(256) kW(const float* __restrict__ fw2)
{
    int i = blockIdx.x * 256 + threadIdx.x;     // 16384
    int h = i >> 12, r = i & 4095;
    int f = r >> 6, j = r & 63;
    g_w2t[i] = fw2[h * 4096 + j * 64 + f];
}

// ---------------- kernel Q: QKV GEMM per (b,h), register-tiled 4t x 12o ----------------
constexpr int Q_XS = 0;            // 64 x 208 (transposed x, stride 208)
constexpr int Q_WT = 13312;        // 64 x 52  (d-major weights)
constexpr int SMEM_Q_BYTES = (13312 + 3328) * 4;   // 66560

__global__ void __launch_bounds__(256, 3) kQ(
    const float* __restrict__ seq, const float* __restrict__ Wqkv)
{
    extern __shared__ float smq[];
    float* xs = smq + Q_XS;
    float* wt = smq + Q_WT;
    const int tid = threadIdx.x;
    const int bid = blockIdx.x;       // 4096 = (b,h)
    const int b = bid >> 2, h = bid & 3;

    // stage x transposed: xs[d*208 + t]  (coalesced global reads)
    const float* xg = seq + (size_t)b * 12800;
    for (int i = tid; i < 12800; i += 256) {
        int t = i >> 6, d = i & 63;
        xs[d * 208 + t] = xg[i];
    }
    // stage weights d-major: wt[d*52 + o];  o: 0-15 q, 16-31 k, 32-47 v
    for (int i = tid; i < 3072; i += 256) {
        int o = i >> 6, d = i & 63;     // d fastest -> coalesced
        int row = (o < 16) ? (h * 16 + o)
                 : (o < 32) ? (64 + h * 16 + (o - 16))
                            : (128 + h * 16 + (o - 32));
        wt[d * 52 + o] = Wqkv[row * 64 + d];
    }
    __syncthreads();

    if (tid >= 200) return;
    const int t0 = (tid % 50) * 4, ob = (tid / 50) * 12;

    u64 acc[4][6];
    #pragma unroll
    for (int tt = 0; tt < 4; tt++)
        #pragma unroll
        for (int p = 0; p < 6; p++) acc[tt][p] = 0ull;

    #pragma unroll 4
    for (int d = 0; d < 64; d++) {
        float4 xv = *(const float4*)&xs[d * 208 + t0];
        u64 xt[4];
        xt[0] = pack2(xv.x, xv.x); xt[1] = pack2(xv.y, xv.y);
        xt[2] = pack2(xv.z, xv.z); xt[3] = pack2(xv.w, xv.w);
        const float* wr = &wt[d * 52 + ob];
        u64 wv[6];
        ld2x(wr,     wv[0], wv[1]);
        ld2x(wr + 4, wv[2], wv[3]);
        ld2x(wr + 8, wv[4], wv[5]);
        #pragma unroll
        for (int tt = 0; tt < 4; tt++)
            #pragma unroll
            for (int p = 0; p < 6; p++)
                acc[tt][p] = fma2(xt[tt], wv[p], acc[tt][p]);
    }

    float* og = g_qkv + (size_t)bid * 9600;
    #pragma unroll
    for (int tt = 0; tt < 4; tt++) {
        float* orow = og + (size_t)(t0 + tt) * 48 + ob;
        F4U u0, u1, u2;
        u0.u[0] = acc[tt][0]; u0.u[1] = acc[tt][1];
        u1.u[0] = acc[tt][2]; u1.u[1] = acc[tt][3];
        u2.u[0] = acc[tt][4]; u2.u[1] = acc[tt][5];
        *(float4*)(orow)     = u0.f;
        *(float4*)(orow + 4) = u1.f;
        *(float4*)(orow + 8) = u2.f;
    }
}

// ---------------- kernel A: attention + W_o/LN + FFN -> ho ----------------
constexpr int OFF_KK = 0;
constexpr int OFF_VV = 4000;
constexpr int OFF_WO = 8000;
constexpr int OFF_R1 = 9024;
constexpr int OFF_LNG = 17216;
constexpr int OFF_LNB = 17280;
constexpr int OFF_B1 = 17344;
constexpr int OFF_B2 = 17408;
constexpr int SMEM_A_FLOATS = 17472;
constexpr int SMEM_A_BYTES = SMEM_A_FLOATS * 4;   // 69888

__global__ void __launch_bounds__(224, 2) kA(
    const float* __restrict__ seq,
    const float* __restrict__ Wo,
    const float* __restrict__ lng, const float* __restrict__ lnb,
    const float* __restrict__ fw1, const float* __restrict__ fb1,
    const float* __restrict__ fb2)
{
    extern __shared__ float sm[];
    float* kk  = sm + OFF_KK;
    float* vv  = sm + OFF_VV;
    float* wo  = sm + OFF_WO;
    float* R1  = sm + OFF_R1;
    float* lngs = sm + OFF_LNG;
    float* lnbs = sm + OFF_LNB;
    float* b1s = sm + OFF_B1;
    float* b2s = sm + OFF_B2;
    float* h1s = sm;               // reuse kk/vv post-attention (6400 <= 8000)

    const int tid = threadIdx.x;
    const int bid = blockIdx.x;
    const int b = bid >> 2, h = bid & 3;

    // ---- single load phase: wo, w1|w2t, vectors, kk/vv from g_qkv ----
    for (int i = tid; i < 1024; i += 224) wo[i] = Wo[h * 1024 + i];
    for (int i = tid; i < 4096; i += 224) {
        R1[i] = fw1[h * 4096 + i];
        R1[4096 + i] = g_w2t[h * 4096 + i];
    }
    if (tid < 64) {
        lngs[tid] = lng[h * 64 + tid];
        lnbs[tid] = lnb[h * 64 + tid];
        b1s[tid]  = fb1[h * 64 + tid];
        b2s[tid]  = fb2[h * 64 + tid];
    }
    const float* qkvg = g_qkv + (size_t)bid * 9600;
    for (int i = tid; i < 3200; i += 224) {
        int t2 = i >> 4, ii = i & 15;
        kk[t2 * 20 + ii] = qkvg[t2 * 48 + 16 + ii];
        vv[t2 * 20 + ii] = qkvg[t2 * 48 + 32 + ii];
    }
    __syncthreads();
    float* w1 = R1;
    float* w2t = R1 + 4096;

    const bool act = tid < 200;
    const int t = act ? tid : 0;

    // ---- q for own token (contiguous 64B) ----
    u64 qp[8];
    if (act) {
        const float* qr = qkvg + (size_t)t * 48;
        ld2x(qr,      qp[0], qp[1]);
        ld2x(qr + 4,  qp[2], qp[3]);
        ld2x(qr + 8,  qp[4], qp[5]);
        ld2x(qr + 12, qp[6], qp[7]);
    }

    u64 sp[32];        // s row -> srg -> ho
    u64 h1b[16];       // h1 second half
    const u64 one2 = pack2(1.f, 1.f);

    if (act) {
        // ---- attention, 2-way interleaved (exp without max: scores bounded) ----
        u64 ctx[8];
        #pragma unroll
        for (int r = 0; r < 8; r++) ctx[r] = 0ull;
        float l = 0.f;
        for (int t2 = 0; t2 < 200; t2 += 2) {
            const float* kr0 = &kk[t2 * 20];
            const float* kr1 = kr0 + 20;
            u64 dA0 = 0, dA1 = 0, dB0 = 0, dB1 = 0, ka, kb;
            ld2x(kr0,      ka, kb); dA0 = fma2(qp[0], ka, dA0); dA1 = fma2(qp[1], kb, dA1);
            ld2x(kr1,      ka, kb); dB0 = fma2(qp[0], ka, dB0); dB1 = fma2(qp[1], kb, dB1);
            ld2x(kr0 + 4,  ka, kb); dA0 = fma2(qp[2], ka, dA0); dA1 = fma2(qp[3], kb, dA1);
            ld2x(kr1 + 4,  ka, kb); dB0 = fma2(qp[2], ka, dB0); dB1 = fma2(qp[3], kb, dB1);
            ld2x(kr0 + 8,  ka, kb); dA0 = fma2(qp[4], ka, dA0); dA1 = fma2(qp[5], kb, dA1);
            ld2x(kr1 + 8,  ka, kb); dB0 = fma2(qp[4], ka, dB0); dB1 = fma2(qp[5], kb, dB1);
            ld2x(kr0 + 12, ka, kb); dA0 = fma2(qp[6], ka, dA0); dA1 = fma2(qp[7], kb, dA1);
            ld2x(kr1 + 12, ka, kb); dB0 = fma2(qp[6], ka, dB0); dB1 = fma2(qp[7], kb, dB1);
            float p0 = __expf((hsum2(dA0) + hsum2(dA1)) * 0.25f);
            float p1 = __expf((hsum2(dB0) + hsum2(dB1)) * 0.25f);
            l += p0 + p1;
            u64 pp0 = pack2(p0, p0), pp1 = pack2(p1, p1);
            const float* vr0 = &vv[t2 * 20];
            const float* vr1 = vr0 + 20;
            u64 va, vb;
            ld2x(vr0,      va, vb); ctx[0] = fma2(pp0, va, ctx[0]); ctx[1] = fma2(pp0, vb, ctx[1]);
            ld2x(vr1,      va, vb); ctx[0] = fma2(pp1, va, ctx[0]); ctx[1] = fma2(pp1, vb, ctx[1]);
            ld2x(vr0 + 4,  va, vb); ctx[2] = fma2(pp0, va, ctx[2]); ctx[3] = fma2(pp0, vb, ctx[3]);
            ld2x(vr1 + 4,  va, vb); ctx[2] = fma2(pp1, va, ctx[2]); ctx[3] = fma2(pp1, vb, ctx[3]);
            ld2x(vr0 + 8,  va, vb); ctx[4] = fma2(pp0, va, ctx[4]); ctx[5] = fma2(pp0, vb, ctx[5]);
            ld2x(vr1 + 8,  va, vb); ctx[4] = fma2(pp1, va, ctx[4]); ctx[5] = fma2(pp1, vb, ctx[5]);
            ld2x(vr0 + 12, va, vb); ctx[6] = fma2(pp0, va, ctx[6]); ctx[7] = fma2(pp0, vb, ctx[7]);
            ld2x(vr1 + 12, va, vb); ctx[6] = fma2(pp1, va, ctx[6]); ctx[7] = fma2(pp1, vb, ctx[7]);
        }
        {
            float rl = 1.f / l;
            u64 rl2 = pack2(rl, rl);
            #pragma unroll
            for (int r = 0; r < 8; r++) ctx[r] = fma2(ctx[r], rl2, 0ull);
        }

        // ---- W_o + residual (x streamed from gmem), LN stats ----
        const float* xr = seq + (size_t)b * 12800 + t * 64;
        u64 mu2 = 0ull, q22 = 0ull;
        #pragma unroll 2
        for (int jp = 0; jp < 32; jp++) {
            const float* wr0 = &wo[(2 * jp) * 16];
            const float* wr1 = wr0 + 16;
            u64 a0 = 0, a1 = 0, b0 = 0, b1 = 0, wa, wb;
            ld2x(wr0,      wa, wb); a0 = fma2(ctx[0], wa, a0); a1 = fma2(ctx[1], wb, a1);
            ld2x(wr0 + 4,  wa, wb); a0 = fma2(ctx[2], wa, a0); a1 = fma2(ctx[3], wb, a1);
            ld2x(wr0 + 8,  wa, wb); a0 = fma2(ctx[4], wa, a0); a1 = fma2(ctx[5], wb, a1);
            ld2x(wr0 + 12, wa, wb); a0 = fma2(ctx[6], wa, a0); a1 = fma2(ctx[7], wb, a1);
            ld2x(wr1,      wa, wb); b0 = fma2(ctx[0], wa, b0); b1 = fma2(ctx[1], wb, b1);
            ld2x(wr1 + 4,  wa, wb); b0 = fma2(ctx[2], wa, b0); b1 = fma2(ctx[3], wb, b1);
            ld2x(wr1 + 8,  wa, wb); b0 = fma2(ctx[4], wa, b0); b1 = fma2(ctx[5], wb, b1);
            ld2x(wr1 + 12, wa, wb); b0 = fma2(ctx[6], wa, b0); b1 = fma2(ctx[7], wb, b1);
            float2 xv = *(const float2*)(xr + 2 * jp);
            float s0 = hsum2(a0) + hsum2(a1) + xv.x;
            float s1 = hsum2(b0) + hsum2(b1) + xv.y;
            u64 spp = pack2(s0, s1);
            sp[jp] = spp;
            mu2 = fma2(spp, one2, mu2);
            q22 = fma2(spp, spp, q22);
        }
        float mu = hsum2(mu2) * (1.f / 64.f);
        float var = hsum2(q22) * (1.f / 64.f) - mu * mu;
        float rstd = rsqrtf(var + 1e-5f);

        // ---- LN in place: sp := srg ----
        {
            u64 rstd2 = pack2(rstd, rstd);
            float nm = -mu * rstd;
            u64 nmr = pack2(nm, nm);
            #pragma unroll
            for (int j4 = 0; j4 < 16; j4++) {
                u64 ga, gb, ba, bb;
                ld2x(&lngs[j4 * 4], ga, gb);
                ld2x(&lnbs[j4 * 4], ba, bb);
                sp[2 * j4]     = fma2(fma2(sp[2 * j4],     rstd2, nmr), ga, ba);
                sp[2 * j4 + 1] = fma2(fma2(sp[2 * j4 + 1], rstd2, nmr), gb, bb);
            }
        }
    }

    __syncthreads();   // all warps past attention: kk/vv region free -> h1s

    if (!act) return;

    // ---- FFN pass1a: f = 0..31 -> h1s (smem) ----
    #pragma unroll 2
    for (int f = 0; f < 32; f++) {
        const float* w1r = &w1[f * 64];
        u64 a0 = 0, a1 = 0, a2 = 0, a3 = 0, wa, wb;
        #pragma unroll
        for (int j4 = 0; j4 < 16; j4 += 2) {
            ld2x(&w1r[j4 * 4], wa, wb);
            a0 = fma2(sp[2 * j4], wa, a0); a1 = fma2(sp[2 * j4 + 1], wb, a1);
            ld2x(&w1r[j4 * 4 + 4], wa, wb);
            a2 = fma2(sp[2 * j4 + 2], wa, a2); a3 = fma2(sp[2 * j4 + 3], wb, a3);
        }
        h1s[f * 200 + t] = fmaxf((hsum2(a0) + hsum2(a1)) + (hsum2(a2) + hsum2(a3)) + b1s[f], 0.f);
    }

    // ---- FFN pass1b: f = 32..63 -> regs ----
    #pragma unroll 2
    for (int fp = 0; fp < 16; fp++) {
        const float* w0 = &w1[(32 + 2 * fp) * 64];
        const float* wB = w0 + 64;
        u64 a0 = 0, a1 = 0, b0 = 0, b1 = 0, wa, wb;
        #pragma unroll
        for (int j4 = 0; j4 < 16; j4++) {
            ld2x(&w0[j4 * 4], wa, wb);
            a0 = fma2(sp[2 * j4], wa, a0); a1 = fma2(sp[2 * j4 + 1], wb, a1);
            ld2x(&wB[j4 * 4], wa, wb);
            b0 = fma2(sp[2 * j4], wa, b0); b1 = fma2(sp[2 * j4 + 1], wb, b1);
        }
        float hA = fmaxf(hsum2(a0) + hsum2(a1) + b1s[32 + 2 * fp], 0.f);
        float hB = fmaxf(hsum2(b0) + hsum2(b1) + b1s[33 + 2 * fp], 0.f);
        h1b[fp] = pack2(hA, hB);
    }

    // ---- sp := srg + b2 (ho accumulator) ----
    #pragma unroll
    for (int j4 = 0; j4 < 16; j4++) {
        u64 ca, cb;
        ld2x(&b2s[j4 * 4], ca, cb);
        sp[2 * j4]     = fma2(sp[2 * j4],     one2, ca);
        sp[2 * j4 + 1] = fma2(sp[2 * j4 + 1], one2, cb);
    }

    // ---- FFN pass2b: consume h1b (f = 32..63) ----
    #pragma unroll 2
    for (int fp = 0; fp < 16; fp++) {
        float hA, hB;
        unpack2(h1b[fp], hA, hB);
        u64 hA2 = pack2(hA, hA), hB2 = pack2(hB, hB);
        const float* r0 = &w2t[(32 + 2 * fp) * 64];
        const float* r1 = r0 + 64;
        u64 wa, wb;
        #pragma unroll
        for (int j4 = 0; j4 < 16; j4++) {
            ld2x(&r0[j4 * 4], wa, wb);
            sp[2 * j4]     = fma2(hA2, wa, sp[2 * j4]);
            sp[2 * j4 + 1] = fma2(hA2, wb, sp[2 * j4 + 1]);
        }
        #pragma unroll
        for (int j4 = 0; j4 < 16; j4++) {
            ld2x(&r1[j4 * 4], wa, wb);
            sp[2 * j4]     = fma2(hB2, wa, sp[2 * j4]);
            sp[2 * j4 + 1] = fma2(hB2, wb, sp[2 * j4 + 1]);
        }
    }

    // ---- FFN pass2a: consume h1s (f = 0..31) ----
    #pragma unroll 2
    for (int f = 0; f < 32; f++) {
        float hf = h1s[f * 200 + t];
        u64 hf2 = pack2(hf, hf);
        const float* r0 = &w2t[f * 64];
        u64 wa, wb;
        #pragma unroll
        for (int j4 = 0; j4 < 16; j4++) {
            ld2x(&r0[j4 * 4], wa, wb);
            sp[2 * j4]     = fma2(hf2, wa, sp[2 * j4]);
            sp[2 * j4 + 1] = fma2(hf2, wb, sp[2 * j4 + 1]);
        }
    }

    // ---- store ho in (d,t) layout (coalesced) ----
    float* hop = g_ho + (size_t)bid * 12800 + t;
    #pragma unroll
    for (int jp = 0; jp < 32; jp++) {
        float a, c;
        unpack2(sp[jp], a, c);
        hop[(2 * jp) * 200] = a;
        hop[(2 * jp + 1) * 200] = c;
    }
}

// ---------------- kernel B0: c1[b,h,f] = mb1 + (W1+W3) te  (coalesced) ----------------
__global__ void __launch_bounds__(128) kB0(
    const float* __restrict__ mw1, const float* __restrict__ mb1,
    const float* __restrict__ targ)
{
    __shared__ float msum[128 * 65];
    __shared__ float tes[64];
    const int tid = threadIdx.x;
    const int bid = blockIdx.x;        // 4096 = (b,h)
    const int b = bid >> 2, h = bid & 3;
    if (tid < 64) tes[tid] = targ[b * 64 + tid];
    const float* m1h = mw1 + (size_t)h * 32768;
    for (int i = tid; i < 8192; i += 128) {
        int f = i >> 6, d = i & 63;     // d fastest -> coalesced
        msum[f * 65 + d] = m1h[f * 256 + d] + m1h[f * 256 + 128 + d];
    }
    __syncthreads();
    float a = mb1[h * 128 + tid];
    const float* mr = &msum[tid * 65];
    #pragma unroll 8
    for (int d = 0; d < 64; d++) a = fmaf(mr[d], tes[d], a);
    g_c1[(size_t)bid * 128 + tid] = a;
}

// ---------------- kernel B: z1 = Weff(b,h) @ ho, two 4t x 8f register-tile passes ----------------
constexpr int B_WT = 0;
constexpr int B_HO = 4352;
constexpr int B_C1 = 17152;
constexpr int B_TE = 17216;
constexpr int SMEM_B_BYTES = 17280 * 4;   // 69120

__global__ void __launch_bounds__(256, 3) kB(
    const float* __restrict__ mw1, const float* __restrict__ targ)
{
    extern __shared__ float smb[];
    float* wt  = smb + B_WT;
    float* hos = smb + B_HO;
    float* c1s = smb + B_C1;
    float* tes = smb + B_TE;

    const int tid = threadIdx.x;
    const int bid = blockIdx.x;          // 8192
    const int bh = bid >> 1, half = bid & 1;
    const int b = bh >> 2, h = bh & 3;

    if (tid < 64) tes[tid] = targ[b * 64 + tid];
    __syncthreads();

    const float* m1h = mw1 + (size_t)h * 32768 + (size_t)half * 64 * 256;
    for (int i = tid; i < 4096; i += 256) {
        int fl = i >> 6, d = i & 63;
        const float* r = m1h + fl * 256;
        wt[d * 68 + fl] = r[64 + d] - r[128 + d] + tes[d] * r[192 + d];
    }
    if (tid < 64) c1s[tid] = g_c1[(size_t)bh * 128 + half * 64 + tid];
    {
        const float4* hop = (const float4*)(g_ho + (size_t)bh * 12800);
        float4* hod = (float4*)hos;
        for (int i = tid; i < 3200; i += 256) hod[i] = hop[i];
    }
    __syncthreads();

    if (tid >= 200) return;
    const int t_tile = tid % 50, ftile = tid / 50;
    const int t0 = t_tile * 4;

    #pragma unroll
    for (int sub = 0; sub < 2; sub++) {
        const int fb = ftile * 16 + sub * 8;

        u64 acc[4][4];
        #pragma unroll
        for (int tt = 0; tt < 4; tt++)
            #pragma unroll
            for (int p = 0; p < 4; p++) acc[tt][p] = 0ull;

        #pragma unroll 4
        for (int d = 0; d < 64; d++) {
            float4 xv = *(const float4*)&hos[d * 200 + t0];
            u64 xt[4];
            xt[0] = pack2(xv.x, xv.x); xt[1] = pack2(xv.y, xv.y);
            xt[2] = pack2(xv.z, xv.z); xt[3] = pack2(xv.w, xv.w);
            const float* wr = &wt[d * 68 + fb];
            u64 wv[4];
            ld2x(wr,     wv[0], wv[1]);
            ld2x(wr + 4, wv[2], wv[3]);
            #pragma unroll
            for (int tt = 0; tt < 4; tt++)
                #pragma unroll
                for (int p = 0; p < 4; p++)
                    acc[tt][p] = fma2(xt[tt], wv[p], acc[tt][p]);
        }

        float* op = g_z1 + (size_t)bh * 25600 + (size_t)(half * 64 + fb) * 200 + t0;
        #pragma unroll
        for (int p = 0; p < 4; p++) {
            float e0, o0, e1, o1, e2, o2, e3, o3;
            unpack2(acc[0][p], e0, o0); unpack2(acc[1][p], e1, o1);
            unpack2(acc[2][p], e2, o2); unpack2(acc[3][p], e3, o3);
            float ce = c1s[fb + 2 * p], co = c1s[fb + 2 * p + 1];
            float4 ve = make_float4(e0 + ce, e1 + ce, e2 + ce, e3 + ce);
            float4 vo = make_float4(o0 + co, o1 + co, o2 + co, o3 + co);
            *(float4*)&op[(size_t)(2 * p) * 200] = ve;
            *(float4*)&op[(size_t)(2 * p + 1) * 200] = vo;
        }
    }
}

// ---------------- stats ----------------
__global__ void __launch_bounds__(256) kP1()
{
    const int bid = blockIdx.x;          // 4096 blocks
    const int j = bid >> 3, sl = bid & 7;
    const int h = j >> 7, f = j & 127;
    const int tid = threadIdx.x;
    float sm = 0.f, sq = 0.f;
    if (tid < 200) {
        const size_t base = ((size_t)h * 128 + f) * 200 + tid;
        for (int b0 = sl * 128; b0 < sl * 128 + 128; b0 += 8) {
            float v0 = g_z1[base + (size_t)(b0 + 0) * 102400];
            float v1 = g_z1[base + (size_t)(b0 + 1) * 102400];
            float v2 = g_z1[base + (size_t)(b0 + 2) * 102400];
            float v3 = g_z1[base + (size_t)(b0 + 3) * 102400];
            float v4 = g_z1[base + (size_t)(b0 + 4) * 102400];
            float v5 = g_z1[base + (size_t)(b0 + 5) * 102400];
            float v6 = g_z1[base + (size_t)(b0 + 6) * 102400];
            float v7 = g_z1[base + (size_t)(b0 + 7) * 102400];
            sm += ((v0 + v1) + (v2 + v3)) + ((v4 + v5) + (v6 + v7));
            sq += fmaf(v0, v0, fmaf(v1, v1, fmaf(v2, v2, v3 * v3)))
                + fmaf(v4, v4, fmaf(v5, v5, fmaf(v6, v6, v7 * v7)));
        }
    }
    __shared__ double rs[256], rq[256];
    rs[tid] = (double)sm; rq[tid] = (double)sq;
    __syncthreads();
    for (int o = 128; o > 0; o >>= 1) {
        if (tid < o) { rs[tid] += rs[tid + o]; rq[tid] += rq[tid + o]; }
        __syncthreads();
    }
    if (tid == 0) { g_p1[bid * 2] = rs[0]; g_p1[bid * 2 + 1] = rq[0]; }
}

__global__ void __launch_bounds__(512) kFin1()
{
    const int j = threadIdx.x;   // 512
    double sm = 0.0, sq = 0.0;
    for (int sl = 0; sl < 8; sl++) {
        sm += g_p1[(j * 8 + sl) * 2];
        sq += g_p1[(j * 8 + sl) * 2 + 1];
    }
    double N = 204800.0;
    double mean = sm / N;
    double var = sq / N - mean * mean;
    if (var < 0.0) var = 0.0;
    g_mean1[j] = (float)mean;
    g_istd1[j] = (float)(1.0 / sqrt(var + 1e-9));
}

__global__ void __launch_bounds__(256) kP2()
{
    const int bid = blockIdx.x;          // 2048 blocks
    const int j = bid >> 3, sl = bid & 7;
    const int h = j >> 6, f = j & 63;
    const int tid = threadIdx.x;
    float sm = 0.f, sq = 0.f;
    if (tid < 200) {
        const size_t base = ((size_t)h * 64 + f) * 200 + tid;
        for (int b0 = sl * 128; b0 < sl * 128 + 128; b0 += 8) {
            float v0 = g_z2[base + (size_t)(b0 + 0) * 51200];
            float v1 = g_z2[base + (size_t)(b0 + 1) * 51200];
            float v2 = g_z2[base + (size_t)(b0 + 2) * 51200];
            float v3 = g_z2[base + (size_t)(b0 + 3) * 51200];
            float v4 = g_z2[base + (size_t)(b0 + 4) * 51200];
            float v5 = g_z2[base + (size_t)(b0 + 5) * 51200];
            float v6 = g_z2[base + (size_t)(b0 + 6) * 51200];
            float v7 = g_z2[base + (size_t)(b0 + 7) * 51200];
            sm += ((v0 + v1) + (v2 + v3)) + ((v4 + v5) + (v6 + v7));
            sq += fmaf(v0, v0, fmaf(v1, v1, fmaf(v2, v2, v3 * v3)))
                + fmaf(v4, v4, fmaf(v5, v5, fmaf(v6, v6, v7 * v7)));
        }
    }
    __shared__ double rs[256], rq[256];
    rs[tid] = (double)sm; rq[tid] = (double)sq;
    __syncthreads();
    for (int o = 128; o > 0; o >>= 1) {
        if (tid < o) { rs[tid] += rs[tid + o]; rq[tid] += rq[tid + o]; }
        __syncthreads();
    }
    if (tid == 0) { g_p2[bid * 2] = rs[0]; g_p2[bid * 2 + 1] = rq[0]; }
}

__global__ void __launch_bounds__(256) kFin2()
{
    const int j = threadIdx.x;   // 256
    double sm = 0.0, sq = 0.0;
    for (int sl = 0; sl < 8; sl++) {
        sm += g_p2[(j * 8 + sl) * 2];
        sq += g_p2[(j * 8 + sl) * 2 + 1];
    }
    double N = 204800.0;
    double mean = sm / N;
    double var = sq / N - mean * mean;
    if (var < 0.0) var = 0.0;
    g_mean2[j] = (float)mean;
    g_istd2[j] = (float)(1.0 / sqrt(var + 1e-9));
}

// ---------------- kernel C: dice1 + mw2 GEMM, pipelined double-buffered staging ----------------
constexpr int C_WS = 0;
constexpr int C_XS = 8192;        // two buffers of 6400
constexpr int C_MN = 20992;
constexpr int C_ISD = 21120;
constexpr int C_AL = 21248;
constexpr int C_MB = 21376;
constexpr int SMEM_C_BYTES = 21440 * 4;   // 85760

__global__ void __launch_bounds__(256, 2) kC(
    const float* __restrict__ mw2, const float* __restrict__ mb2,
    const float* __restrict__ alpha1)
{
    extern __shared__ float smc[];
    float* ws  = smc + C_WS;
    float* xs  = smc + C_XS;
    float* mn  = smc + C_MN;
    float* isd = smc + C_ISD;
    float* al  = smc + C_AL;
    float* mbs = smc + C_MB;

    const int tid = threadIdx.x, bh = blockIdx.x;
    const int h = bh & 3;

    for (int i = tid; i < 8192; i += 256) {
        int f = i >> 6, g = i & 63;
        ws[i] = mw2[(size_t)h * 8192 + g * 128 + f];
    }
    if (tid < 128) {
        int j = h * 128 + tid;
        mn[tid] = g_mean1[j]; isd[tid] = g_istd1[j]; al[tid] = alpha1[j];
    } else if (tid < 192) {
        mbs[tid - 128] = mb2[h * 64 + (tid - 128)];
    }
    __syncthreads();

    const float* zbase = g_z1 + (size_t)bh * 25600;

    #pragma unroll
    for (int k = 0; k < 25; k++) {
        int i = tid + k * 256;
        int f = i / 200;
        float zv = zbase[i];
        float xa = (zv - mn[f]) * isd[f];
        float p = __fdividef(1.f, 1.f + __expf(-xa));
        xs[i] = (p + al[f] * (1.f - p)) * zv;
    }
    __syncthreads();

    const bool act = tid < 200;
    const int t_tile = tid % 50, g_tile = tid / 50;
    const int t0 = t_tile * 4, gb = (g_tile < 4 ? g_tile : 0) * 16;

    u64 acc[4][8];
    #pragma unroll
    for (int t = 0; t < 4; t++)
        #pragma unroll
        for (int p = 0; p < 8; p++) acc[t][p] = 0ull;

    float pre[25];

    for (int ft = 0; ft < 4; ft++) {
        if (ft < 3) {
            const float* zp = zbase + (ft + 1) * 6400;
            #pragma unroll
            for (int k = 0; k < 25; k++) pre[k] = zp[tid + k * 256];
        }
        const float* xcur = xs + (ft & 1) * 6400;
        if (act) {
            #pragma unroll 4
            for (int f = 0; f < 32; f++) {
                float4 xv = *(const float4*)&xcur[f * 200 + t0];
                u64 xt[4];
                xt[0] = pack2(xv.x, xv.x); xt[1] = pack2(xv.y, xv.y);
                xt[2] = pack2(xv.z, xv.z); xt[3] = pack2(xv.w, xv.w);
                const float* wr = &ws[(ft * 32 + f) * 64 + gb];
                u64 wv[8];
                ld2x(wr,      wv[0], wv[1]);
                ld2x(wr + 4,  wv[2], wv[3]);
                ld2x(wr + 8,  wv[4], wv[5]);
                ld2x(wr + 12, wv[6], wv[7]);
                #pragma unroll
                for (int t = 0; t < 4; t++)
                    #pragma unroll
                    for (int p = 0; p < 8; p++)
                        acc[t][p] = fma2(xt[t], wv[p], acc[t][p]);
            }
        }
        if (ft < 3) {
            __syncthreads();
            float* xn = xs + ((ft + 1) & 1) * 6400;
            const int fbase = (ft + 1) * 32;
            #pragma unroll
            for (int k = 0; k < 25; k++) {
                int i = tid + k * 256;
                int fg = fbase + i / 200;
                float zv = pre[k];
                float xa = (zv - mn[fg]) * isd[fg];
                float p = __fdividef(1.f, 1.f + __expf(-xa));
                xn[i] = (p + al[fg] * (1.f - p)) * zv;
            }
            __syncthreads();
        }
    }

    if (act) {
        float* op = g_z2 + (size_t)bh * 12800 + t0;
        #pragma unroll
        for (int p = 0; p < 8; p++) {
            float e0, o0, e1, o1, e2, o2, e3, o3;
            unpack2(acc[0][p], e0, o0); unpack2(acc[1][p], e1, o1);
            unpack2(acc[2][p], e2, o2); unpack2(acc[3][p], e3, o3);
            int ge = gb + 2 * p, go = ge + 1;
            float be = mbs[ge], bo = mbs[go];
            float4 ve = make_float4(e0 + be, e1 + be, e2 + be, e3 + be);
            float4 vo = make_float4(o0 + bo, o1 + bo, o2 + bo, o3 + bo);
            *(float4*)&op[(size_t)ge * 200] = ve;
            *(float4*)&op[(size_t)go * 200] = vo;
        }
    }
}

// ---------------- kernel E: dice2 + score + softmax + pooling ----------------
__global__ void __launch_bounds__(256) kE(
    const int* __restrict__ mask, const float* __restrict__ mw3,
    const float* __restrict__ mb3, const float* __restrict__ alpha2,
    float* __restrict__ out)
{
    __shared__ float w3s[64], m2s[64], i2s[64], a2s[64];
    __shared__ float red[256];
    __shared__ float wts[200];
    const int tid = threadIdx.x, bid = blockIdx.x;
    const int b = bid >> 2, h = bid & 3;
    if (tid < 64) {
        int j = h * 64 + tid;
        w3s[tid] = mw3[j]; m2s[tid] = g_mean2[j]; i2s[tid] = g_istd2[j]; a2s[tid] = alpha2[j];
    }
    __syncthreads();

    float sc = -3.0e38f;
    if (tid < 200) {
        const float* zp = g_z2 + (size_t)bid * 12800 + tid;
        float a = 0.f;
        #pragma unroll 4
        for (int g = 0; g < 64; g++) {
            float zv = zp[g * 200];
            float xa = (zv - m2s[g]) * i2s[g];
            float p = __fdividef(1.f, 1.f + __expf(-xa));
            float xv = (p + a2s[g] * (1.f - p)) * zv;
            a = fmaf(xv, w3s[g], a);
        }
        sc = a + mb3[h];
        if (mask[b * 200 + tid] == 0) sc = -1e9f;
    }
    red[tid] = sc;
    __syncthreads();
    for (int o = 128; o > 0; o >>= 1) {
        if (tid < o) red[tid] = fmaxf(red[tid], red[tid + o]);
        __syncthreads();
    }
    float mx = red[0];
    __syncthreads();
    float e = (tid < 200) ? __expf(sc - mx) : 0.f;
    red[tid] = e;
    __syncthreads();
    for (int o = 128; o > 0; o >>= 1) {
        if (tid < o) red[tid] += red[tid + o];
        __syncthreads();
    }
    float inv = 1.f / red[0];
    if (tid < 200) wts[tid] = e * inv;
    __syncthreads();

    const int c = tid >> 6, d = tid & 63;
    const float* hp = g_ho + (size_t)bid * 12800 + d * 200 + c * 50;
    float acc = 0.f;
    #pragma unroll 2
    for (int i = 0; i < 50; i++)
        acc = fmaf(wts[c * 50 + i], hp[i], acc);
    red[tid] = acc;
    __syncthreads();
    if (tid < 64)
        out[(size_t)bid * 64 + tid] = (red[tid] + red[tid + 64]) + (red[tid + 128] + red[tid + 192]);
}

// ---------------- launch ----------------
extern "C" void kernel_launch(void* const* d_in, const int* in_sizes, int n_in,
                              void* d_out, int out_size)
{
    const float* seq  = (const float*)d_in[0];
    const float* targ = (const float*)d_in[1];
    const int*   mask = (const int*)d_in[2];
    const float* Wqkv = (const float*)d_in[3];
    const float* Wo   = (const float*)d_in[4];
    const float* lng  = (const float*)d_in[5];
    const float* lnb  = (const float*)d_in[6];
    const float* fw1  = (const float*)d_in[7];
    const float* fb1  = (const float*)d_in[8];
    const float* fw2  = (const float*)d_in[9];
    const float* fb2  = (const float*)d_in[10];
    const float* mw1  = (const float*)d_in[11];
    const float* mb1  = (const float*)d_in[12];
    const float* a1   = (const float*)d_in[13];
    const float* mw2  = (const float*)d_in[14];
    const float* mb2  = (const float*)d_in[15];
    const float* a2   = (const float*)d_in[16];
    const float* mw3  = (const float*)d_in[17];
    const float* mb3  = (const float*)d_in[18];
    float* out = (float*)d_out;

    cudaFuncSetAttribute(kQ, cudaFuncAttributeMaxDynamicSharedMemorySize, SMEM_Q_BYTES);
    cudaFuncSetAttribute(kA, cudaFuncAttributeMaxDynamicSharedMemorySize, SMEM_A_BYTES);
    cudaFuncSetAttribute(kB, cudaFuncAttributeMaxDynamicSharedMemorySize, SMEM_B_BYTES);
    cudaFuncSetAttribute(kC, cudaFuncAttributeMaxDynamicSharedMemorySize, SMEM_C_BYTES);

    kW<<<64, 256>>>(fw2);
    kB0<<<4096, 128>>>(mw1, mb1, targ);
    kQ<<<4096, 256, SMEM_Q_BYTES>>>(seq, Wqkv);
    kA<<<4096, 224, SMEM_A_BYTES>>>(seq, Wo, lng, lnb, fw1, fb1, fb2);
    kB<<<8192, 256, SMEM_B_BYTES>>>(mw1, targ);
    kP1<<<4096, 256>>>();
    kFin1<<<1, 512>>>();
    kC<<<4096, 256, SMEM_C_BYTES>>>(mw2, mb2, a1);
    kP2<<<2048, 256>>>();
    kFin2<<<1, 256>>>();
    kE<<<4096, 256>>>(mask, mw3, mb3, a2, out);
}

// round 15
// speedup vs baseline: 1.0417x; 1.0417x over previous
#include <cuda_runtime.h>
#include <math.h>

typedef unsigned long long u64;

// ---------------- f32x2 packed helpers ----------------
__device__ __forceinline__ u64 fma2(u64 a, u64 b, u64 c) {
    u64 d; asm("fma.rn.f32x2 %0, %1, %2, %3;" : "=l"(d) : "l"(a), "l"(b), "l"(c)); return d;
}
__device__ __forceinline__ u64 pack2(float x, float y) {
    u64 r; asm("mov.b64 %0, {%1, %2};" : "=l"(r) : "f"(x), "f"(y)); return r;
}
__device__ __forceinline__ float hsum2(u64 v) {
    float a, b; asm("mov.b64 {%0, %1}, %2;" : "=f"(a), "=f"(b) : "l"(v)); return a + b;
}
__device__ __forceinline__ void unpack2(u64 v, float& a, float& b) {
    asm("mov.b64 {%0, %1}, %2;" : "=f"(a), "=f"(b) : "l"(v));
}
union F4U { float4 f; u64 u[2]; };
__device__ __forceinline__ void ld2x(const float* p, u64& a, u64& b) {
    F4U t; t.f = *(const float4*)p; a = t.u[0]; b = t.u[1];
}

// ---------------- scratch (no allocs allowed) ----------------
__device__ float g_ho[52428800];    // (b,h,d,t)  210 MB
__device__ float g_z1[104857600];   // (b,h,f,t)  419 MB
__device__ float g_z2[52428800];    // (b,h,g,t)  210 MB
__device__ float g_c1[524288];      // (b,h,f)    2 MB
__device__ float g_w2t[16384];      // transposed ffn_w2 [h][f][j]
__device__ double g_p1[4096 * 2];
__device__ float g_ps2s[262144];    // stats2 partials: [j=256][b=1024]
__device__ float g_ps2q[262144];
__device__ float g_mean1[512], g_istd1[512];
__device__ float g_mean2[256], g_istd2[256];

// ---------------- kernel W: one-shot transpose of ffn_w2 ----------------
__global__ void __launch_bounds__(256) kW(const float* __restrict__ fw2)
{
    int i = blockIdx.x * 256 + threadIdx.x;     // 16384
    int h = i >> 12, r = i & 4095;
    int f = r >> 6, j = r & 63;
    g_w2t[i] = fw2[h * 4096 + j * 64 + f];
}

// ---------------- kernel A: QKV + attention + W_o/LN + FFN -> ho ----------------
constexpr int OFF_KK = 0;
constexpr int OFF_VV = 4000;
constexpr int OFF_WO = 8000;
constexpr int OFF_R1 = 9024;
constexpr int OFF_LNG = 17216;
constexpr int OFF_LNB = 17280;
constexpr int OFF_B1 = 17344;
constexpr int OFF_B2 = 17408;
constexpr int SMEM_A_FLOATS = 17472;
constexpr int SMEM_A_BYTES = SMEM_A_FLOATS * 4;   // 69888

__global__ void __launch_bounds__(224, 2) kA(
    const float* __restrict__ seq,
    const float* __restrict__ Wqkv, const float* __restrict__ Wo,
    const float* __restrict__ lng, const float* __restrict__ lnb,
    const float* __restrict__ fw1, const float* __restrict__ fb1,
    const float* __restrict__ fb2)
{
    extern __shared__ float sm[];
    float* kk  = sm + OFF_KK;
    float* vv  = sm + OFF_VV;
    float* wo  = sm + OFF_WO;
    float* R1  = sm + OFF_R1;
    float* lngs = sm + OFF_LNG;
    float* lnbs = sm + OFF_LNB;
    float* b1s = sm + OFF_B1;
    float* b2s = sm + OFF_B2;
    float* h1s = sm;               // reuse kk/vv post-attention (6400 <= 8000)

    const int tid = threadIdx.x;
    const int bid = blockIdx.x;
    const int b = bid >> 2, h = bid & 3;

    // ---- phase-1 loads: qkv weights + wo + vectors ----
    for (int i = tid; i < 1024; i += 224) {
        int r = i >> 6, d = i & 63;
        R1[i]        = Wqkv[(h * 16 + r) * 64 + d];
        R1[1024 + i] = Wqkv[(64 + h * 16 + r) * 64 + d];
        R1[2048 + i] = Wqkv[(128 + h * 16 + r) * 64 + d];
        wo[i] = Wo[h * 1024 + i];
    }
    if (tid < 64) {
        lngs[tid] = lng[h * 64 + tid];
        lnbs[tid] = lnb[h * 64 + tid];
        b1s[tid]  = fb1[h * 64 + tid];
        b2s[tid]  = fb2[h * 64 + tid];
    }
    __syncthreads();

    const bool act = tid < 200;
    const int t = act ? tid : 0;
    const int t20 = t * 20;

    // ---- QKV: thread = token; q -> regs, k/v -> smem ----
    u64 qp[8];
    if (act) {
        u64 xp[32];
        const float* xr = seq + (size_t)b * 12800 + t * 64;
        #pragma unroll
        for (int j4 = 0; j4 < 16; j4++) ld2x(xr + j4 * 4, xp[2 * j4], xp[2 * j4 + 1]);
        float qv[16];
        #pragma unroll 4
        for (int i = 0; i < 16; i++) {
            u64 q0 = 0, q1 = 0, k0 = 0, k1 = 0, v0 = 0, v1 = 0, wa, wb;
            #pragma unroll
            for (int j4 = 0; j4 < 16; j4++) {
                ld2x(R1 + i * 64 + j4 * 4, wa, wb);
                q0 = fma2(xp[2 * j4], wa, q0); q1 = fma2(xp[2 * j4 + 1], wb, q1);
                ld2x(R1 + 1024 + i * 64 + j4 * 4, wa, wb);
                k0 = fma2(xp[2 * j4], wa, k0); k1 = fma2(xp[2 * j4 + 1], wb, k1);
                ld2x(R1 + 2048 + i * 64 + j4 * 4, wa, wb);
                v0 = fma2(xp[2 * j4], wa, v0); v1 = fma2(xp[2 * j4 + 1], wb, v1);
            }
            qv[i] = hsum2(q0) + hsum2(q1);
            kk[t20 + i] = hsum2(k0) + hsum2(k1);
            vv[t20 + i] = hsum2(v0) + hsum2(v1);
        }
        #pragma unroll
        for (int ip = 0; ip < 8; ip++) qp[ip] = pack2(qv[2 * ip], qv[2 * ip + 1]);
    }
    __syncthreads();   // QKV done; R1 free for w1/w2t

    // ---- phase-2 loads: w1 | w2t into R1 (both coalesced) ----
    for (int i = tid; i < 4096; i += 224) {
        R1[i] = fw1[h * 4096 + i];
        R1[4096 + i] = g_w2t[h * 4096 + i];
    }
    __syncthreads();
    float* w1 = R1;
    float* w2t = R1 + 4096;

    u64 sp[32];        // s row -> srg -> ho
    u64 h1b[16];       // h1 second half
    const u64 one2 = pack2(1.f, 1.f);

    if (act) {
        // ---- attention, 2-way interleaved (exp without max: scores bounded) ----
        u64 ctx[8];
        #pragma unroll
        for (int r = 0; r < 8; r++) ctx[r] = 0ull;
        float l = 0.f;
        for (int t2 = 0; t2 < 200; t2 += 2) {
            const float* kr0 = &kk[t2 * 20];
            const float* kr1 = kr0 + 20;
            u64 dA0 = 0, dA1 = 0, dB0 = 0, dB1 = 0, ka, kb;
            ld2x(kr0,      ka, kb); dA0 = fma2(qp[0], ka, dA0); dA1 = fma2(qp[1], kb, dA1);
            ld2x(kr1,      ka, kb); dB0 = fma2(qp[0], ka, dB0); dB1 = fma2(qp[1], kb, dB1);
            ld2x(kr0 + 4,  ka, kb); dA0 = fma2(qp[2], ka, dA0); dA1 = fma2(qp[3], kb, dA1);
            ld2x(kr1 + 4,  ka, kb); dB0 = fma2(qp[2], ka, dB0); dB1 = fma2(qp[3], kb, dB1);
            ld2x(kr0 + 8,  ka, kb); dA0 = fma2(qp[4], ka, dA0); dA1 = fma2(qp[5], kb, dA1);
            ld2x(kr1 + 8,  ka, kb); dB0 = fma2(qp[4], ka, dB0); dB1 = fma2(qp[5], kb, dB1);
            ld2x(kr0 + 12, ka, kb); dA0 = fma2(qp[6], ka, dA0); dA1 = fma2(qp[7], kb, dA1);
            ld2x(kr1 + 12, ka, kb); dB0 = fma2(qp[6], ka, dB0); dB1 = fma2(qp[7], kb, dB1);
            float p0 = __expf((hsum2(dA0) + hsum2(dA1)) * 0.25f);
            float p1 = __expf((hsum2(dB0) + hsum2(dB1)) * 0.25f);
            l += p0 + p1;
            u64 pp0 = pack2(p0, p0), pp1 = pack2(p1, p1);
            const float* vr0 = &vv[t2 * 20];
            const float* vr1 = vr0 + 20;
            u64 va, vb;
            ld2x(vr0,      va, vb); ctx[0] = fma2(pp0, va, ctx[0]); ctx[1] = fma2(pp0, vb, ctx[1]);
            ld2x(vr1,      va, vb); ctx[0] = fma2(pp1, va, ctx[0]); ctx[1] = fma2(pp1, vb, ctx[1]);
            ld2x(vr0 + 4,  va, vb); ctx[2] = fma2(pp0, va, ctx[2]); ctx[3] = fma2(pp0, vb, ctx[3]);
            ld2x(vr1 + 4,  va, vb); ctx[2] = fma2(pp1, va, ctx[2]); ctx[3] = fma2(pp1, vb, ctx[3]);
            ld2x(vr0 + 8,  va, vb); ctx[4] = fma2(pp0, va, ctx[4]); ctx[5] = fma2(pp0, vb, ctx[5]);
            ld2x(vr1 + 8,  va, vb); ctx[4] = fma2(pp1, va, ctx[4]); ctx[5] = fma2(pp1, vb, ctx[5]);
            ld2x(vr0 + 12, va, vb); ctx[6] = fma2(pp0, va, ctx[6]); ctx[7] = fma2(pp0, vb, ctx[7]);
            ld2x(vr1 + 12, va, vb); ctx[6] = fma2(pp1, va, ctx[6]); ctx[7] = fma2(pp1, vb, ctx[7]);
        }
        {
            float rl = 1.f / l;
            u64 rl2 = pack2(rl, rl);
            #pragma unroll
            for (int r = 0; r < 8; r++) ctx[r] = fma2(ctx[r], rl2, 0ull);
        }

        // ---- W_o + residual (x streamed from gmem), LN stats ----
        const float* xr = seq + (size_t)b * 12800 + t * 64;
        u64 mu2 = 0ull, q22 = 0ull;
        #pragma unroll 2
        for (int jp = 0; jp < 32; jp++) {
            const float* wr0 = &wo[(2 * jp) * 16];
            const float* wr1 = wr0 + 16;
            u64 a0 = 0, a1 = 0, b0 = 0, b1 = 0, wa, wb;
            ld2x(wr0,      wa, wb); a0 = fma2(ctx[0], wa, a0); a1 = fma2(ctx[1], wb, a1);
            ld2x(wr0 + 4,  wa, wb); a0 = fma2(ctx[2], wa, a0); a1 = fma2(ctx[3], wb, a1);
            ld2x(wr0 + 8,  wa, wb); a0 = fma2(ctx[4], wa, a0); a1 = fma2(ctx[5], wb, a1);
            ld2x(wr0 + 12, wa, wb); a0 = fma2(ctx[6], wa, a0); a1 = fma2(ctx[7], wb, a1);
            ld2x(wr1,      wa, wb); b0 = fma2(ctx[0], wa, b0); b1 = fma2(ctx[1], wb, b1);
            ld2x(wr1 + 4,  wa, wb); b0 = fma2(ctx[2], wa, b0); b1 = fma2(ctx[3], wb, b1);
            ld2x(wr1 + 8,  wa, wb); b0 = fma2(ctx[4], wa, b0); b1 = fma2(ctx[5], wb, b1);
            ld2x(wr1 + 12, wa, wb); b0 = fma2(ctx[6], wa, b0); b1 = fma2(ctx[7], wb, b1);
            float2 xv = *(const float2*)(xr + 2 * jp);
            float s0 = hsum2(a0) + hsum2(a1) + xv.x;
            float s1 = hsum2(b0) + hsum2(b1) + xv.y;
            u64 spp = pack2(s0, s1);
            sp[jp] = spp;
            mu2 = fma2(spp, one2, mu2);
            q22 = fma2(spp, spp, q22);
        }
        float mu = hsum2(mu2) * (1.f / 64.f);
        float var = hsum2(q22) * (1.f / 64.f) - mu * mu;
        float rstd = rsqrtf(var + 1e-5f);

        // ---- LN in place: sp := srg ----
        {
            u64 rstd2 = pack2(rstd, rstd);
            float nm = -mu * rstd;
            u64 nmr = pack2(nm, nm);
            #pragma unroll
            for (int j4 = 0; j4 < 16; j4++) {
                u64 ga, gb, ba, bb;
                ld2x(&lngs[j4 * 4], ga, gb);
                ld2x(&lnbs[j4 * 4], ba, bb);
                sp[2 * j4]     = fma2(fma2(sp[2 * j4],     rstd2, nmr), ga, ba);
                sp[2 * j4 + 1] = fma2(fma2(sp[2 * j4 + 1], rstd2, nmr), gb, bb);
            }
        }
    }

    __syncthreads();   // all warps past attention: kk/vv region free -> h1s

    if (!act) return;

    // ---- FFN pass1a: f = 0..31 -> h1s (smem) ----
    #pragma unroll 2
    for (int f = 0; f < 32; f++) {
        const float* w1r = &w1[f * 64];
        u64 a0 = 0, a1 = 0, a2 = 0, a3 = 0, wa, wb;
        #pragma unroll
        for (int j4 = 0; j4 < 16; j4 += 2) {
            ld2x(&w1r[j4 * 4], wa, wb);
            a0 = fma2(sp[2 * j4], wa, a0); a1 = fma2(sp[2 * j4 + 1], wb, a1);
            ld2x(&w1r[j4 * 4 + 4], wa, wb);
            a2 = fma2(sp[2 * j4 + 2], wa, a2); a3 = fma2(sp[2 * j4 + 3], wb, a3);
        }
        h1s[f * 200 + t] = fmaxf((hsum2(a0) + hsum2(a1)) + (hsum2(a2) + hsum2(a3)) + b1s[f], 0.f);
    }

    // ---- FFN pass1b: f = 32..63 -> regs ----
    #pragma unroll 2
    for (int fp = 0; fp < 16; fp++) {
        const float* w0 = &w1[(32 + 2 * fp) * 64];
        const float* wB = w0 + 64;
        u64 a0 = 0, a1 = 0, b0 = 0, b1 = 0, wa, wb;
        #pragma unroll
        for (int j4 = 0; j4 < 16; j4++) {
            ld2x(&w0[j4 * 4], wa, wb);
            a0 = fma2(sp[2 * j4], wa, a0); a1 = fma2(sp[2 * j4 + 1], wb, a1);
            ld2x(&wB[j4 * 4], wa, wb);
            b0 = fma2(sp[2 * j4], wa, b0); b1 = fma2(sp[2 * j4 + 1], wb, b1);
        }
        float hA = fmaxf(hsum2(a0) + hsum2(a1) + b1s[32 + 2 * fp], 0.f);
        float hB = fmaxf(hsum2(b0) + hsum2(b1) + b1s[33 + 2 * fp], 0.f);
        h1b[fp] = pack2(hA, hB);
    }

    // ---- sp := srg + b2 (ho accumulator) ----
    #pragma unroll
    for (int j4 = 0; j4 < 16; j4++) {
        u64 ca, cb;
        ld2x(&b2s[j4 * 4], ca, cb);
        sp[2 * j4]     = fma2(sp[2 * j4],     one2, ca);
        sp[2 * j4 + 1] = fma2(sp[2 * j4 + 1], one2, cb);
    }

    // ---- FFN pass2b: consume h1b (f = 32..63) ----
    #pragma unroll 2
    for (int fp = 0; fp < 16; fp++) {
        float hA, hB;
        unpack2(h1b[fp], hA, hB);
        u64 hA2 = pack2(hA, hA), hB2 = pack2(hB, hB);
        const float* r0 = &w2t[(32 + 2 * fp) * 64];
        const float* r1 = r0 + 64;
        u64 wa, wb;
        #pragma unroll
        for (int j4 = 0; j4 < 16; j4++) {
            ld2x(&r0[j4 * 4], wa, wb);
            sp[2 * j4]     = fma2(hA2, wa, sp[2 * j4]);
            sp[2 * j4 + 1] = fma2(hA2, wb, sp[2 * j4 + 1]);
        }
        #pragma unroll
        for (int j4 = 0; j4 < 16; j4++) {
            ld2x(&r1[j4 * 4], wa, wb);
            sp[2 * j4]     = fma2(hB2, wa, sp[2 * j4]);
            sp[2 * j4 + 1] = fma2(hB2, wb, sp[2 * j4 + 1]);
        }
    }

    // ---- FFN pass2a: consume h1s (f = 0..31) ----
    #pragma unroll 2
    for (int f = 0; f < 32; f++) {
        float hf = h1s[f * 200 + t];
        u64 hf2 = pack2(hf, hf);
        const float* r0 = &w2t[f * 64];
        u64 wa, wb;
        #pragma unroll
        for (int j4 = 0; j4 < 16; j4++) {
            ld2x(&r0[j4 * 4], wa, wb);
            sp[2 * j4]     = fma2(hf2, wa, sp[2 * j4]);
            sp[2 * j4 + 1] = fma2(hf2, wb, sp[2 * j4 + 1]);
        }
    }

    // ---- store ho in (d,t) layout (coalesced) ----
    float* hop = g_ho + (size_t)bid * 12800 + t;
    #pragma unroll
    for (int jp = 0; jp < 32; jp++) {
        float a, c;
        unpack2(sp[jp], a, c);
        hop[(2 * jp) * 200] = a;
        hop[(2 * jp + 1) * 200] = c;
    }
}

// ---------------- kernel B0: c1[b,h,f] = mb1 + (W1+W3) te  (coalesced) ----------------
__global__ void __launch_bounds__(128) kB0(
    const float* __restrict__ mw1, const float* __restrict__ mb1,
    const float* __restrict__ targ)
{
    __shared__ float msum[128 * 65];
    __shared__ float tes[64];
    const int tid = threadIdx.x;
    const int bid = blockIdx.x;        // 4096 = (b,h)
    const int b = bid >> 2, h = bid & 3;
    if (tid < 64) tes[tid] = targ[b * 64 + tid];
    const float* m1h = mw1 + (size_t)h * 32768;
    for (int i = tid; i < 8192; i += 128) {
        int f = i >> 6, d = i & 63;     // d fastest -> coalesced
        msum[f * 65 + d] = m1h[f * 256 + d] + m1h[f * 256 + 128 + d];
    }
    __syncthreads();
    float a = mb1[h * 128 + tid];
    const float* mr = &msum[tid * 65];
    #pragma unroll 8
    for (int d = 0; d < 64; d++) a = fmaf(mr[d], tes[d], a);
    g_c1[(size_t)bid * 128 + tid] = a;
}

// ---------------- kernel B: z1 = Weff(b,h) @ ho, two 4t x 8f register-tile passes ----------------
constexpr int B_WT = 0;
constexpr int B_HO = 4352;
constexpr int B_C1 = 17152;
constexpr int B_TE = 17216;
constexpr int SMEM_B_BYTES = 17280 * 4;   // 69120

__global__ void __launch_bounds__(256, 3) kB(
    const float* __restrict__ mw1, const float* __restrict__ targ)
{
    extern __shared__ float smb[];
    float* wt  = smb + B_WT;
    float* hos = smb + B_HO;
    float* c1s = smb + B_C1;
    float* tes = smb + B_TE;

    const int tid = threadIdx.x;
    const int bid = blockIdx.x;          // 8192
    const int bh = bid >> 1, half = bid & 1;
    const int b = bh >> 2, h = bh & 3;

    if (tid < 64) tes[tid] = targ[b * 64 + tid];
    __syncthreads();

    const float* m1h = mw1 + (size_t)h * 32768 + (size_t)half * 64 * 256;
    for (int i = tid; i < 4096; i += 256) {
        int fl = i >> 6, d = i & 63;
        const float* r = m1h + fl * 256;
        wt[d * 68 + fl] = r[64 + d] - r[128 + d] + tes[d] * r[192 + d];
    }
    if (tid < 64) c1s[tid] = g_c1[(size_t)bh * 128 + half * 64 + tid];
    {
        const float4* hop = (const float4*)(g_ho + (size_t)bh * 12800);
        float4* hod = (float4*)hos;
        for (int i = tid; i < 3200; i += 256) hod[i] = hop[i];
    }
    __syncthreads();

    if (tid >= 200) return;
    const int t_tile = tid % 50, ftile = tid / 50;
    const int t0 = t_tile * 4;

    #pragma unroll
    for (int sub = 0; sub < 2; sub++) {
        const int fb = ftile * 16 + sub * 8;

        u64 acc[4][4];
        #pragma unroll
        for (int tt = 0; tt < 4; tt++)
            #pragma unroll
            for (int p = 0; p < 4; p++) acc[tt][p] = 0ull;

        #pragma unroll 4
        for (int d = 0; d < 64; d++) {
            float4 xv = *(const float4*)&hos[d * 200 + t0];
            u64 xt[4];
            xt[0] = pack2(xv.x, xv.x); xt[1] = pack2(xv.y, xv.y);
            xt[2] = pack2(xv.z, xv.z); xt[3] = pack2(xv.w, xv.w);
            const float* wr = &wt[d * 68 + fb];
            u64 wv[4];
            ld2x(wr,     wv[0], wv[1]);
            ld2x(wr + 4, wv[2], wv[3]);
            #pragma unroll
            for (int tt = 0; tt < 4; tt++)
                #pragma unroll
                for (int p = 0; p < 4; p++)
                    acc[tt][p] = fma2(xt[tt], wv[p], acc[tt][p]);
        }

        float* op = g_z1 + (size_t)bh * 25600 + (size_t)(half * 64 + fb) * 200 + t0;
        #pragma unroll
        for (int p = 0; p < 4; p++) {
            float e0, o0, e1, o1, e2, o2, e3, o3;
            unpack2(acc[0][p], e0, o0); unpack2(acc[1][p], e1, o1);
            unpack2(acc[2][p], e2, o2); unpack2(acc[3][p], e3, o3);
            float ce = c1s[fb + 2 * p], co = c1s[fb + 2 * p + 1];
            float4 ve = make_float4(e0 + ce, e1 + ce, e2 + ce, e3 + ce);
            float4 vo = make_float4(o0 + co, o1 + co, o2 + co, o3 + co);
            *(float4*)&op[(size_t)(2 * p) * 200] = ve;
            *(float4*)&op[(size_t)(2 * p + 1) * 200] = vo;
        }
    }
}

// ---------------- stats-1 (z1) ----------------
__global__ void __launch_bounds__(256) kP1()
{
    const int bid = blockIdx.x;          // 4096 blocks
    const int j = bid >> 3, sl = bid & 7;
    const int h = j >> 7, f = j & 127;
    const int tid = threadIdx.x;
    float sm = 0.f, sq = 0.f;
    if (tid < 200) {
        const size_t base = ((size_t)h * 128 + f) * 200 + tid;
        for (int b0 = sl * 128; b0 < sl * 128 + 128; b0 += 8) {
            float v0 = g_z1[base + (size_t)(b0 + 0) * 102400];
            float v1 = g_z1[base + (size_t)(b0 + 1) * 102400];
            float v2 = g_z1[base + (size_t)(b0 + 2) * 102400];
            float v3 = g_z1[base + (size_t)(b0 + 3) * 102400];
            float v4 = g_z1[base + (size_t)(b0 + 4) * 102400];
            float v5 = g_z1[base + (size_t)(b0 + 5) * 102400];
            float v6 = g_z1[base + (size_t)(b0 + 6) * 102400];
            float v7 = g_z1[base + (size_t)(b0 + 7) * 102400];
            sm += ((v0 + v1) + (v2 + v3)) + ((v4 + v5) + (v6 + v7));
            sq += fmaf(v0, v0, fmaf(v1, v1, fmaf(v2, v2, v3 * v3)))
                + fmaf(v4, v4, fmaf(v5, v5, fmaf(v6, v6, v7 * v7)));
        }
    }
    __shared__ double rs[256], rq[256];
    rs[tid] = (double)sm; rq[tid] = (double)sq;
    __syncthreads();
    for (int o = 128; o > 0; o >>= 1) {
        if (tid < o) { rs[tid] += rs[tid + o]; rq[tid] += rq[tid + o]; }
        __syncthreads();
    }
    if (tid == 0) { g_p1[bid * 2] = rs[0]; g_p1[bid * 2 + 1] = rq[0]; }
}

__global__ void __launch_bounds__(512) kFin1()
{
    const int j = threadIdx.x;   // 512
    double sm = 0.0, sq = 0.0;
    for (int sl = 0; sl < 8; sl++) {
        sm += g_p1[(j * 8 + sl) * 2];
        sq += g_p1[(j * 8 + sl) * 2 + 1];
    }
    double N = 204800.0;
    double mean = sm / N;
    double var = sq / N - mean * mean;
    if (var < 0.0) var = 0.0;
    g_mean1[j] = (float)mean;
    g_istd1[j] = (float)(1.0 / sqrt(var + 1e-9));
}

// ---------------- stats-2 finalize (partials written by kC epilogue) ----------------
__global__ void __launch_bounds__(256) kFin2()
{
    const int j = blockIdx.x;   // 256
    const int tid = threadIdx.x;
    double sm = 0.0, sq = 0.0;
    for (int b = tid; b < 1024; b += 256) {
        sm += (double)g_ps2s[j * 1024 + b];
        sq += (double)g_ps2q[j * 1024 + b];
    }
    __shared__ double rs[256], rq[256];
    rs[tid] = sm; rq[tid] = sq;
    __syncthreads();
    for (int o = 128; o > 0; o >>= 1) {
        if (tid < o) { rs[tid] += rs[tid + o]; rq[tid] += rq[tid + o]; }
        __syncthreads();
    }
    if (tid == 0) {
        double N = 204800.0;
        double mean = rs[0] / N;
        double var = rq[0] / N - mean * mean;
        if (var < 0.0) var = 0.0;
        g_mean2[j] = (float)mean;
        g_istd2[j] = (float)(1.0 / sqrt(var + 1e-9));
    }
}

// ---------------- kernel C: dice1 + mw2 GEMM, pipelined + fused stats-2 epilogue ----------------
constexpr int C_WS = 0;
constexpr int C_XS = 8192;        // two buffers of 6400
constexpr int C_MN = 20992;
constexpr int C_ISD = 21120;
constexpr int C_AL = 21248;
constexpr int C_MB = 21376;
constexpr int SMEM_C_BYTES = 21440 * 4;   // 85760

__global__ void __launch_bounds__(256, 2) kC(
    const float* __restrict__ mw2, const float* __restrict__ mb2,
    const float* __restrict__ alpha1)
{
    extern __shared__ float smc[];
    float* ws  = smc + C_WS;
    float* xs  = smc + C_XS;
    float* mn  = smc + C_MN;
    float* isd = smc + C_ISD;
    float* al  = smc + C_AL;
    float* mbs = smc + C_MB;

    const int tid = threadIdx.x, bh = blockIdx.x;
    const int b = bh >> 2, h = bh & 3;

    for (int i = tid; i < 8192; i += 256) {
        int f = i >> 6, g = i & 63;
        ws[i] = mw2[(size_t)h * 8192 + g * 128 + f];
    }
    if (tid < 128) {
        int j = h * 128 + tid;
        mn[tid] = g_mean1[j]; isd[tid] = g_istd1[j]; al[tid] = alpha1[j];
    } else if (tid < 192) {
        mbs[tid - 128] = mb2[h * 64 + (tid - 128)];
    }
    __syncthreads();   // mn/isd/al ready before dice

    const float* zbase = g_z1 + (size_t)bh * 25600;

    // prologue: stage phase 0 into buffer 0
    #pragma unroll
    for (int k = 0; k < 25; k++) {
        int i = tid + k * 256;
        int f = i / 200;
        float zv = zbase[i];
        float xa = (zv - mn[f]) * isd[f];
        float p = __fdividef(1.f, 1.f + __expf(-xa));
        xs[i] = (p + al[f] * (1.f - p)) * zv;
    }
    __syncthreads();

    const bool act = tid < 200;
    const int t_tile = tid % 50, g_tile = tid / 50;
    const int t0 = t_tile * 4, gb = (g_tile < 4 ? g_tile : 0) * 16;

    u64 acc[4][8];
    #pragma unroll
    for (int t = 0; t < 4; t++)
        #pragma unroll
        for (int p = 0; p < 8; p++) acc[t][p] = 0ull;

    float pre[25];

    for (int ft = 0; ft < 4; ft++) {
        if (ft < 3) {
            const float* zp = zbase + (ft + 1) * 6400;
            #pragma unroll
            for (int k = 0; k < 25; k++) pre[k] = zp[tid + k * 256];
        }
        const float* xcur = xs + (ft & 1) * 6400;
        if (act) {
            #pragma unroll 4
            for (int f = 0; f < 32; f++) {
                float4 xv = *(const float4*)&xcur[f * 200 + t0];
                u64 xt[4];
                xt[0] = pack2(xv.x, xv.x); xt[1] = pack2(xv.y, xv.y);
                xt[2] = pack2(xv.z, xv.z); xt[3] = pack2(xv.w, xv.w);
                const float* wr = &ws[(ft * 32 + f) * 64 + gb];
                u64 wv[8];
                ld2x(wr,      wv[0], wv[1]);
                ld2x(wr + 4,  wv[2], wv[3]);
                ld2x(wr + 8,  wv[4], wv[5]);
                ld2x(wr + 12, wv[6], wv[7]);
                #pragma unroll
                for (int t = 0; t < 4; t++)
                    #pragma unroll
                    for (int p = 0; p < 8; p++)
                        acc[t][p] = fma2(xt[t], wv[p], acc[t][p]);
            }
        }
        if (ft < 3) {
            __syncthreads();
            float* xn = xs + ((ft + 1) & 1) * 6400;
            const int fbase = (ft + 1) * 32;
            #pragma unroll
            for (int k = 0; k < 25; k++) {
                int i = tid + k * 256;
                int fg = fbase + i / 200;
                float zv = pre[k];
                float xa = (zv - mn[fg]) * isd[fg];
                float p = __fdividef(1.f, 1.f + __expf(-xa));
                xn[i] = (p + al[fg] * (1.f - p)) * zv;
            }
            __syncthreads();
        }
    }

    // all ws reads done (last in ft=3 compute) -> reuse ws for stats partials
    __syncthreads();
    float* ps = ws;            // [g*50 + t_tile] per-thread sums
    float* pq = ws + 3200;

    if (act) {
        float* op = g_z2 + (size_t)bh * 12800 + t0;
        #pragma unroll
        for (int p = 0; p < 8; p++) {
            float e0, o0, e1, o1, e2, o2, e3, o3;
            unpack2(acc[0][p], e0, o0); unpack2(acc[1][p], e1, o1);
            unpack2(acc[2][p], e2, o2); unpack2(acc[3][p], e3, o3);
            int ge = gb + 2 * p, go = ge + 1;
            float be = mbs[ge], bo = mbs[go];
            float4 ve = make_float4(e0 + be, e1 + be, e2 + be, e3 + be);
            float4 vo = make_float4(o0 + bo, o1 + bo, o2 + bo, o3 + bo);
            *(float4*)&op[(size_t)ge * 200] = ve;
            *(float4*)&op[(size_t)go * 200] = vo;
            // stats partials (deterministic order)
            ps[ge * 50 + t_tile] = ((ve.x + ve.y) + (ve.z + ve.w));
            pq[ge * 50 + t_tile] = fmaf(ve.x, ve.x, fmaf(ve.y, ve.y, fmaf(ve.z, ve.z, ve.w * ve.w)));
            ps[go * 50 + t_tile] = ((vo.x + vo.y) + (vo.z + vo.w));
            pq[go * 50 + t_tile] = fmaf(vo.x, vo.x, fmaf(vo.y, vo.y, fmaf(vo.z, vo.z, vo.w * vo.w)));
        }
    }
    __syncthreads();

    if (tid < 64) {
        float sm = 0.f, sq = 0.f;
        const float* pr = &ps[tid * 50];
        const float* qr = &pq[tid * 50];
        #pragma unroll 5
        for (int i = 0; i < 50; i++) { sm += pr[i]; sq += qr[i]; }
        int j = h * 64 + tid;
        g_ps2s[j * 1024 + b] = sm;
        g_ps2q[j * 1024 + b] = sq;
    }
}

// ---------------- kernel E: dice2 + score + softmax + pooling ----------------
__global__ void __launch_bounds__(256) kE(
    const int* __restrict__ mask, const float* __restrict__ mw3,
    const float* __restrict__ mb3, const float* __restrict__ alpha2,
    float* __restrict__ out)
{
    __shared__ float w3s[64], m2s[64], i2s[64], a2s[64];
    __shared__ float red[256];
    __shared__ float wts[200];
    const int tid = threadIdx.x, bid = blockIdx.x;
    const int b = bid >> 2, h = bid & 3;
    if (tid < 64) {
        int j = h * 64 + tid;
        w3s[tid] = mw3[j]; m2s[tid] = g_mean2[j]; i2s[tid] = g_istd2[j]; a2s[tid] = alpha2[j];
    }
    __syncthreads();

    float sc = -3.0e38f;
    if (tid < 200) {
        const float* zp = g_z2 + (size_t)bid * 12800 + tid;
        float a = 0.f;
        #pragma unroll 4
        for (int g = 0; g < 64; g++) {
            float zv = zp[g * 200];
            float xa = (zv - m2s[g]) * i2s[g];
            float p = __fdividef(1.f, 1.f + __expf(-xa));
            float xv = (p + a2s[g] * (1.f - p)) * zv;
            a = fmaf(xv, w3s[g], a);
        }
        sc = a + mb3[h];
        if (mask[b * 200 + tid] == 0) sc = -1e9f;
    }
    red[tid] = sc;
    __syncthreads();
    for (int o = 128; o > 0; o >>= 1) {
        if (tid < o) red[tid] = fmaxf(red[tid], red[tid + o]);
        __syncthreads();
    }
    float mx = red[0];
    __syncthreads();
    float e = (tid < 200) ? __expf(sc - mx) : 0.f;
    red[tid] = e;
    __syncthreads();
    for (int o = 128; o > 0; o >>= 1) {
        if (tid < o) red[tid] += red[tid + o];
        __syncthreads();
    }
    float inv = 1.f / red[0];
    if (tid < 200) wts[tid] = e * inv;
    __syncthreads();

    const int c = tid >> 6, d = tid & 63;
    const float* hp = g_ho + (size_t)bid * 12800 + d * 200 + c * 50;
    float acc = 0.f;
    #pragma unroll 2
    for (int i = 0; i < 50; i++)
        acc = fmaf(wts[c * 50 + i], hp[i], acc);
    red[tid] = acc;
    __syncthreads();
    if (tid < 64)
        out[(size_t)bid * 64 + tid] = (red[tid] + red[tid + 64]) + (red[tid + 128] + red[tid + 192]);
}

// ---------------- launch ----------------
extern "C" void kernel_launch(void* const* d_in, const int* in_sizes, int n_in,
                              void* d_out, int out_size)
{
    const float* seq  = (const float*)d_in[0];
    const float* targ = (const float*)d_in[1];
    const int*   mask = (const int*)d_in[2];
    const float* Wqkv = (const float*)d_in[3];
    const float* Wo   = (const float*)d_in[4];
    const float* lng  = (const float*)d_in[5];
    const float* lnb  = (const float*)d_in[6];
    const float* fw1  = (const float*)d_in[7];
    const float* fb1  = (const float*)d_in[8];
    const float* fw2  = (const float*)d_in[9];
    const float* fb2  = (const float*)d_in[10];
    const float* mw1  = (const float*)d_in[11];
    const float* mb1  = (const float*)d_in[12];
    const float* a1   = (const float*)d_in[13];
    const float* mw2  = (const float*)d_in[14];
    const float* mb2  = (const float*)d_in[15];
    const float* a2   = (const float*)d_in[16];
    const float* mw3  = (const float*)d_in[17];
    const float* mb3  = (const float*)d_in[18];
    float* out = (float*)d_out;

    cudaFuncSetAttribute(kA, cudaFuncAttributeMaxDynamicSharedMemorySize, SMEM_A_BYTES);
    cudaFuncSetAttribute(kB, cudaFuncAttributeMaxDynamicSharedMemorySize, SMEM_B_BYTES);
    cudaFuncSetAttribute(kC, cudaFuncAttributeMaxDynamicSharedMemorySize, SMEM_C_BYTES);

    kW<<<64, 256>>>(fw2);
    kB0<<<4096, 128>>>(mw1, mb1, targ);
    kA<<<4096, 224, SMEM_A_BYTES>>>(seq, Wqkv, Wo, lng, lnb, fw1, fb1, fb2);
    kB<<<8192, 256, SMEM_B_BYTES>>>(mw1, targ);
    kP1<<<4096, 256>>>();
    kFin1<<<1, 512>>>();
    kC<<<4096, 256, SMEM_C_BYTES>>>(mw2, mb2, a1);
    kFin2<<<256, 256>>>();
    kE<<<4096, 256>>>(mask, mw3, mb3, a2, out);
}

// round 16
// speedup vs baseline: 1.0491x; 1.0071x over previous
#include <cuda_runtime.h>
#include <math.h>

typedef unsigned long long u64;

// ---------------- f32x2 packed helpers ----------------
__device__ __forceinline__ u64 fma2(u64 a, u64 b, u64 c) {
    u64 d; asm("fma.rn.f32x2 %0, %1, %2, %3;" : "=l"(d) : "l"(a), "l"(b), "l"(c)); return d;
}
__device__ __forceinline__ u64 pack2(float x, float y) {
    u64 r; asm("mov.b64 %0, {%1, %2};" : "=l"(r) : "f"(x), "f"(y)); return r;
}
__device__ __forceinline__ float hsum2(u64 v) {
    float a, b; asm("mov.b64 {%0, %1}, %2;" : "=f"(a), "=f"(b) : "l"(v)); return a + b;
}
__device__ __forceinline__ void unpack2(u64 v, float& a, float& b) {
    asm("mov.b64 {%0, %1}, %2;" : "=f"(a), "=f"(b) : "l"(v));
}
union F4U { float4 f; u64 u[2]; };
__device__ __forceinline__ void ld2x(const float* p, u64& a, u64& b) {
    F4U t; t.f = *(const float4*)p; a = t.u[0]; b = t.u[1];
}

// ---------------- scratch (no allocs allowed) ----------------
__device__ float g_ho[52428800];    // (b,h,d,t)  210 MB
__device__ float g_z1[104857600];   // (b,h,f,t)  419 MB
__device__ float g_z2[52428800];    // (b,h,g,t)  210 MB
__device__ float g_c1[524288];      // (b,h,f)    2 MB
__device__ float g_w2t[16384];      // transposed ffn_w2 [h][f][j]
__device__ double g_p1[4096 * 2];
__device__ float g_ps2s[262144];    // stats2 partials: [j=256][b=1024]
__device__ float g_ps2q[262144];
__device__ float g_mean1[512], g_istd1[512];
__device__ float g_mean2[256], g_istd2[256];

// ---------------- kernel W: one-shot transpose of ffn_w2 ----------------
__global__ void __launch_bounds__(256) kW(const float* __restrict__ fw2)
{
    int i = blockIdx.x * 256 + threadIdx.x;     // 16384
    int h = i >> 12, r = i & 4095;
    int f = r >> 6, j = r & 63;
    g_w2t[i] = fw2[h * 4096 + j * 64 + f];
}

// ---------------- kernel A: QKV + attention + W_o/LN + FFN -> ho ----------------
constexpr int OFF_KK = 0;
constexpr int OFF_VV = 4000;
constexpr int OFF_WO = 8000;
constexpr int OFF_R1 = 9024;
constexpr int OFF_LNG = 17216;
constexpr int OFF_LNB = 17280;
constexpr int OFF_B1 = 17344;
constexpr int OFF_B2 = 17408;
constexpr int SMEM_A_FLOATS = 17472;
constexpr int SMEM_A_BYTES = SMEM_A_FLOATS * 4;   // 69888

__global__ void __launch_bounds__(224, 2) kA(
    const float* __restrict__ seq,
    const float* __restrict__ Wqkv, const float* __restrict__ Wo,
    const float* __restrict__ lng, const float* __restrict__ lnb,
    const float* __restrict__ fw1, const float* __restrict__ fb1,
    const float* __restrict__ fb2)
{
    extern __shared__ float sm[];
    float* kk  = sm + OFF_KK;
    float* vv  = sm + OFF_VV;
    float* wo  = sm + OFF_WO;
    float* R1  = sm + OFF_R1;
    float* lngs = sm + OFF_LNG;
    float* lnbs = sm + OFF_LNB;
    float* b1s = sm + OFF_B1;
    float* b2s = sm + OFF_B2;
    float* h1s = sm;               // reuse kk/vv post-attention (6400 <= 8000)

    const int tid = threadIdx.x;
    const int bid = blockIdx.x;
    const int b = bid >> 2, h = bid & 3;

    // ---- phase-1 loads: qkv weights + wo + vectors ----
    for (int i = tid; i < 1024; i += 224) {
        int r = i >> 6, d = i & 63;
        R1[i]        = Wqkv[(h * 16 + r) * 64 + d];
        R1[1024 + i] = Wqkv[(64 + h * 16 + r) * 64 + d];
        R1[2048 + i] = Wqkv[(128 + h * 16 + r) * 64 + d];
        wo[i] = Wo[h * 1024 + i];
    }
    if (tid < 64) {
        lngs[tid] = lng[h * 64 + tid];
        lnbs[tid] = lnb[h * 64 + tid];
        b1s[tid]  = fb1[h * 64 + tid];
        b2s[tid]  = fb2[h * 64 + tid];
    }
    __syncthreads();

    const bool act = tid < 200;
    const int t = act ? tid : 0;
    const int t20 = t * 20;

    // ---- QKV: thread = token; q -> regs, k/v -> smem ----
    u64 qp[8];
    if (act) {
        u64 xp[32];
        const float* xr = seq + (size_t)b * 12800 + t * 64;
        #pragma unroll
        for (int j4 = 0; j4 < 16; j4++) ld2x(xr + j4 * 4, xp[2 * j4], xp[2 * j4 + 1]);
        float qv[16];
        #pragma unroll 4
        for (int i = 0; i < 16; i++) {
            u64 q0 = 0, q1 = 0, k0 = 0, k1 = 0, v0 = 0, v1 = 0, wa, wb;
            #pragma unroll
            for (int j4 = 0; j4 < 16; j4++) {
                ld2x(R1 + i * 64 + j4 * 4, wa, wb);
                q0 = fma2(xp[2 * j4], wa, q0); q1 = fma2(xp[2 * j4 + 1], wb, q1);
                ld2x(R1 + 1024 + i * 64 + j4 * 4, wa, wb);
                k0 = fma2(xp[2 * j4], wa, k0); k1 = fma2(xp[2 * j4 + 1], wb, k1);
                ld2x(R1 + 2048 + i * 64 + j4 * 4, wa, wb);
                v0 = fma2(xp[2 * j4], wa, v0); v1 = fma2(xp[2 * j4 + 1], wb, v1);
            }
            qv[i] = hsum2(q0) + hsum2(q1);
            kk[t20 + i] = hsum2(k0) + hsum2(k1);
            vv[t20 + i] = hsum2(v0) + hsum2(v1);
        }
        #pragma unroll
        for (int ip = 0; ip < 8; ip++) qp[ip] = pack2(qv[2 * ip], qv[2 * ip + 1]);
    }
    __syncthreads();   // QKV done; R1 free for w1/w2t

    // ---- phase-2 loads: w1 | w2t into R1 (both coalesced) ----
    for (int i = tid; i < 4096; i += 224) {
        R1[i] = fw1[h * 4096 + i];
        R1[4096 + i] = g_w2t[h * 4096 + i];
    }
    __syncthreads();
    float* w1 = R1;
    float* w2t = R1 + 4096;

    u64 sp[32];        // s row -> srg -> ho
    u64 h1b[16];       // h1 second half
    const u64 one2 = pack2(1.f, 1.f);

    if (act) {
        // ---- attention, 4-way interleaved (exp without max: scores bounded) ----
        u64 ctx[8];
        #pragma unroll
        for (int r = 0; r < 8; r++) ctx[r] = 0ull;
        float l = 0.f;
        for (int t2 = 0; t2 < 200; t2 += 4) {
            const float* kr0 = &kk[t2 * 20];
            const float* kr1 = kr0 + 20;
            const float* kr2 = kr0 + 40;
            const float* kr3 = kr0 + 60;
            u64 dA0 = 0, dA1 = 0, dB0 = 0, dB1 = 0;
            u64 dC0 = 0, dC1 = 0, dD0 = 0, dD1 = 0;
            u64 ka, kb;
            ld2x(kr0,      ka, kb); dA0 = fma2(qp[0], ka, dA0); dA1 = fma2(qp[1], kb, dA1);
            ld2x(kr1,      ka, kb); dB0 = fma2(qp[0], ka, dB0); dB1 = fma2(qp[1], kb, dB1);
            ld2x(kr2,      ka, kb); dC0 = fma2(qp[0], ka, dC0); dC1 = fma2(qp[1], kb, dC1);
            ld2x(kr3,      ka, kb); dD0 = fma2(qp[0], ka, dD0); dD1 = fma2(qp[1], kb, dD1);
            ld2x(kr0 + 4,  ka, kb); dA0 = fma2(qp[2], ka, dA0); dA1 = fma2(qp[3], kb, dA1);
            ld2x(kr1 + 4,  ka, kb); dB0 = fma2(qp[2], ka, dB0); dB1 = fma2(qp[3], kb, dB1);
            ld2x(kr2 + 4,  ka, kb); dC0 = fma2(qp[2], ka, dC0); dC1 = fma2(qp[3], kb, dC1);
            ld2x(kr3 + 4,  ka, kb); dD0 = fma2(qp[2], ka, dD0); dD1 = fma2(qp[3], kb, dD1);
            ld2x(kr0 + 8,  ka, kb); dA0 = fma2(qp[4], ka, dA0); dA1 = fma2(qp[5], kb, dA1);
            ld2x(kr1 + 8,  ka, kb); dB0 = fma2(qp[4], ka, dB0); dB1 = fma2(qp[5], kb, dB1);
            ld2x(kr2 + 8,  ka, kb); dC0 = fma2(qp[4], ka, dC0); dC1 = fma2(qp[5], kb, dC1);
            ld2x(kr3 + 8,  ka, kb); dD0 = fma2(qp[4], ka, dD0); dD1 = fma2(qp[5], kb, dD1);
            ld2x(kr0 + 12, ka, kb); dA0 = fma2(qp[6], ka, dA0); dA1 = fma2(qp[7], kb, dA1);
            ld2x(kr1 + 12, ka, kb); dB0 = fma2(qp[6], ka, dB0); dB1 = fma2(qp[7], kb, dB1);
            ld2x(kr2 + 12, ka, kb); dC0 = fma2(qp[6], ka, dC0); dC1 = fma2(qp[7], kb, dC1);
            ld2x(kr3 + 12, ka, kb); dD0 = fma2(qp[6], ka, dD0); dD1 = fma2(qp[7], kb, dD1);
            float p0 = __expf((hsum2(dA0) + hsum2(dA1)) * 0.25f);
            float p1 = __expf((hsum2(dB0) + hsum2(dB1)) * 0.25f);
            float p2 = __expf((hsum2(dC0) + hsum2(dC1)) * 0.25f);
            float p3 = __expf((hsum2(dD0) + hsum2(dD1)) * 0.25f);
            l += (p0 + p1) + (p2 + p3);
            u64 pp0 = pack2(p0, p0), pp1 = pack2(p1, p1);
            u64 pp2 = pack2(p2, p2), pp3 = pack2(p3, p3);
            const float* vr0 = &vv[t2 * 20];
            const float* vr1 = vr0 + 20;
            const float* vr2 = vr0 + 40;
            const float* vr3 = vr0 + 60;
            u64 va, vb;
            ld2x(vr0,      va, vb); ctx[0] = fma2(pp0, va, ctx[0]); ctx[1] = fma2(pp0, vb, ctx[1]);
            ld2x(vr1,      va, vb); ctx[0] = fma2(pp1, va, ctx[0]); ctx[1] = fma2(pp1, vb, ctx[1]);
            ld2x(vr2,      va, vb); ctx[0] = fma2(pp2, va, ctx[0]); ctx[1] = fma2(pp2, vb, ctx[1]);
            ld2x(vr3,      va, vb); ctx[0] = fma2(pp3, va, ctx[0]); ctx[1] = fma2(pp3, vb, ctx[1]);
            ld2x(vr0 + 4,  va, vb); ctx[2] = fma2(pp0, va, ctx[2]); ctx[3] = fma2(pp0, vb, ctx[3]);
            ld2x(vr1 + 4,  va, vb); ctx[2] = fma2(pp1, va, ctx[2]); ctx[3] = fma2(pp1, vb, ctx[3]);
            ld2x(vr2 + 4,  va, vb); ctx[2] = fma2(pp2, va, ctx[2]); ctx[3] = fma2(pp2, vb, ctx[3]);
            ld2x(vr3 + 4,  va, vb); ctx[2] = fma2(pp3, va, ctx[2]); ctx[3] = fma2(pp3, vb, ctx[3]);
            ld2x(vr0 + 8,  va, vb); ctx[4] = fma2(pp0, va, ctx[4]); ctx[5] = fma2(pp0, vb, ctx[5]);
            ld2x(vr1 + 8,  va, vb); ctx[4] = fma2(pp1, va, ctx[4]); ctx[5] = fma2(pp1, vb, ctx[5]);
            ld2x(vr2 + 8,  va, vb); ctx[4] = fma2(pp2, va, ctx[4]); ctx[5] = fma2(pp2, vb, ctx[5]);
            ld2x(vr3 + 8,  va, vb); ctx[4] = fma2(pp3, va, ctx[4]); ctx[5] = fma2(pp3, vb, ctx[5]);
            ld2x(vr0 + 12, va, vb); ctx[6] = fma2(pp0, va, ctx[6]); ctx[7] = fma2(pp0, vb, ctx[7]);
            ld2x(vr1 + 12, va, vb); ctx[6] = fma2(pp1, va, ctx[6]); ctx[7] = fma2(pp1, vb, ctx[7]);
            ld2x(vr2 + 12, va, vb); ctx[6] = fma2(pp2, va, ctx[6]); ctx[7] = fma2(pp2, vb, ctx[7]);
            ld2x(vr3 + 12, va, vb); ctx[6] = fma2(pp3, va, ctx[6]); ctx[7] = fma2(pp3, vb, ctx[7]);
        }
        {
            float rl = 1.f / l;
            u64 rl2 = pack2(rl, rl);
            #pragma unroll
            for (int r = 0; r < 8; r++) ctx[r] = fma2(ctx[r], rl2, 0ull);
        }

        // ---- W_o + residual (x streamed from gmem), LN stats ----
        const float* xr = seq + (size_t)b * 12800 + t * 64;
        u64 mu2 = 0ull, q22 = 0ull;
        #pragma unroll 2
        for (int jp = 0; jp < 32; jp++) {
            const float* wr0 = &wo[(2 * jp) * 16];
            const float* wr1 = wr0 + 16;
            u64 a0 = 0, a1 = 0, b0 = 0, b1 = 0, wa, wb;
            ld2x(wr0,      wa, wb); a0 = fma2(ctx[0], wa, a0); a1 = fma2(ctx[1], wb, a1);
            ld2x(wr0 + 4,  wa, wb); a0 = fma2(ctx[2], wa, a0); a1 = fma2(ctx[3], wb, a1);
            ld2x(wr0 + 8,  wa, wb); a0 = fma2(ctx[4], wa, a0); a1 = fma2(ctx[5], wb, a1);
            ld2x(wr0 + 12, wa, wb); a0 = fma2(ctx[6], wa, a0); a1 = fma2(ctx[7], wb, a1);
            ld2x(wr1,      wa, wb); b0 = fma2(ctx[0], wa, b0); b1 = fma2(ctx[1], wb, b1);
            ld2x(wr1 + 4,  wa, wb); b0 = fma2(ctx[2], wa, b0); b1 = fma2(ctx[3], wb, b1);
            ld2x(wr1 + 8,  wa, wb); b0 = fma2(ctx[4], wa, b0); b1 = fma2(ctx[5], wb, b1);
            ld2x(wr1 + 12, wa, wb); b0 = fma2(ctx[6], wa, b0); b1 = fma2(ctx[7], wb, b1);
            float2 xv = *(const float2*)(xr + 2 * jp);
            float s0 = hsum2(a0) + hsum2(a1) + xv.x;
            float s1 = hsum2(b0) + hsum2(b1) + xv.y;
            u64 spp = pack2(s0, s1);
            sp[jp] = spp;
            mu2 = fma2(spp, one2, mu2);
            q22 = fma2(spp, spp, q22);
        }
        float mu = hsum2(mu2) * (1.f / 64.f);
        float var = hsum2(q22) * (1.f / 64.f) - mu * mu;
        float rstd = rsqrtf(var + 1e-5f);

        // ---- LN in place: sp := srg ----
        {
            u64 rstd2 = pack2(rstd, rstd);
            float nm = -mu * rstd;
            u64 nmr = pack2(nm, nm);
            #pragma unroll
            for (int j4 = 0; j4 < 16; j4++) {
                u64 ga, gb, ba, bb;
                ld2x(&lngs[j4 * 4], ga, gb);
                ld2x(&lnbs[j4 * 4], ba, bb);
                sp[2 * j4]     = fma2(fma2(sp[2 * j4],     rstd2, nmr), ga, ba);
                sp[2 * j4 + 1] = fma2(fma2(sp[2 * j4 + 1], rstd2, nmr), gb, bb);
            }
        }
    }

    __syncthreads();   // all warps past attention: kk/vv region free -> h1s

    if (!act) return;

    // ---- FFN pass1a: f = 0..31 -> h1s (smem) ----
    #pragma unroll 2
    for (int f = 0; f < 32; f++) {
        const float* w1r = &w1[f * 64];
        u64 a0 = 0, a1 = 0, a2 = 0, a3 = 0, wa, wb;
        #pragma unroll
        for (int j4 = 0; j4 < 16; j4 += 2) {
            ld2x(&w1r[j4 * 4], wa, wb);
            a0 = fma2(sp[2 * j4], wa, a0); a1 = fma2(sp[2 * j4 + 1], wb, a1);
            ld2x(&w1r[j4 * 4 + 4], wa, wb);
            a2 = fma2(sp[2 * j4 + 2], wa, a2); a3 = fma2(sp[2 * j4 + 3], wb, a3);
        }
        h1s[f * 200 + t] = fmaxf((hsum2(a0) + hsum2(a1)) + (hsum2(a2) + hsum2(a3)) + b1s[f], 0.f);
    }

    // ---- FFN pass1b: f = 32..63 -> regs ----
    #pragma unroll 2
    for (int fp = 0; fp < 16; fp++) {
        const float* w0 = &w1[(32 + 2 * fp) * 64];
        const float* wB = w0 + 64;
        u64 a0 = 0, a1 = 0, b0 = 0, b1 = 0, wa, wb;
        #pragma unroll
        for (int j4 = 0; j4 < 16; j4++) {
            ld2x(&w0[j4 * 4], wa, wb);
            a0 = fma2(sp[2 * j4], wa, a0); a1 = fma2(sp[2 * j4 + 1], wb, a1);
            ld2x(&wB[j4 * 4], wa, wb);
            b0 = fma2(sp[2 * j4], wa, b0); b1 = fma2(sp[2 * j4 + 1], wb, b1);
        }
        float hA = fmaxf(hsum2(a0) + hsum2(a1) + b1s[32 + 2 * fp], 0.f);
        float hB = fmaxf(hsum2(b0) + hsum2(b1) + b1s[33 + 2 * fp], 0.f);
        h1b[fp] = pack2(hA, hB);
    }

    // ---- sp := srg + b2 (ho accumulator) ----
    #pragma unroll
    for (int j4 = 0; j4 < 16; j4++) {
        u64 ca, cb;
        ld2x(&b2s[j4 * 4], ca, cb);
        sp[2 * j4]     = fma2(sp[2 * j4],     one2, ca);
        sp[2 * j4 + 1] = fma2(sp[2 * j4 + 1], one2, cb);
    }

    // ---- FFN pass2b: consume h1b (f = 32..63) ----
    #pragma unroll 2
    for (int fp = 0; fp < 16; fp++) {
        float hA, hB;
        unpack2(h1b[fp], hA, hB);
        u64 hA2 = pack2(hA, hA), hB2 = pack2(hB, hB);
        const float* r0 = &w2t[(32 + 2 * fp) * 64];
        const float* r1 = r0 + 64;
        u64 wa, wb;
        #pragma unroll
        for (int j4 = 0; j4 < 16; j4++) {
            ld2x(&r0[j4 * 4], wa, wb);
            sp[2 * j4]     = fma2(hA2, wa, sp[2 * j4]);
            sp[2 * j4 + 1] = fma2(hA2, wb, sp[2 * j4 + 1]);
        }
        #pragma unroll
        for (int j4 = 0; j4 < 16; j4++) {
            ld2x(&r1[j4 * 4], wa, wb);
            sp[2 * j4]     = fma2(hB2, wa, sp[2 * j4]);
            sp[2 * j4 + 1] = fma2(hB2, wb, sp[2 * j4 + 1]);
        }
    }

    // ---- FFN pass2a: consume h1s (f = 0..31) ----
    #pragma unroll 2
    for (int f = 0; f < 32; f++) {
        float hf = h1s[f * 200 + t];
        u64 hf2 = pack2(hf, hf);
        const float* r0 = &w2t[f * 64];
        u64 wa, wb;
        #pragma unroll
        for (int j4 = 0; j4 < 16; j4++) {
            ld2x(&r0[j4 * 4], wa, wb);
            sp[2 * j4]     = fma2(hf2, wa, sp[2 * j4]);
            sp[2 * j4 + 1] = fma2(hf2, wb, sp[2 * j4 + 1]);
        }
    }

    // ---- store ho in (d,t) layout (coalesced) ----
    float* hop = g_ho + (size_t)bid * 12800 + t;
    #pragma unroll
    for (int jp = 0; jp < 32; jp++) {
        float a, c;
        unpack2(sp[jp], a, c);
        hop[(2 * jp) * 200] = a;
        hop[(2 * jp + 1) * 200] = c;
    }
}

// ---------------- kernel B0: c1[b,h,f] = mb1 + (W1+W3) te  (coalesced) ----------------
__global__ void __launch_bounds__(128) kB0(
    const float* __restrict__ mw1, const float* __restrict__ mb1,
    const float* __restrict__ targ)
{
    __shared__ float msum[128 * 65];
    __shared__ float tes[64];
    const int tid = threadIdx.x;
    const int bid = blockIdx.x;        // 4096 = (b,h)
    const int b = bid >> 2, h = bid & 3;
    if (tid < 64) tes[tid] = targ[b * 64 + tid];
    const float* m1h = mw1 + (size_t)h * 32768;
    for (int i = tid; i < 8192; i += 128) {
        int f = i >> 6, d = i & 63;     // d fastest -> coalesced
        msum[f * 65 + d] = m1h[f * 256 + d] + m1h[f * 256 + 128 + d];
    }
    __syncthreads();
    float a = mb1[h * 128 + tid];
    const float* mr = &msum[tid * 65];
    #pragma unroll 8
    for (int d = 0; d < 64; d++) a = fmaf(mr[d], tes[d], a);
    g_c1[(size_t)bid * 128 + tid] = a;
}

// ---------------- kernel B: z1 = Weff(b,h) @ ho, two 4t x 8f register-tile passes ----------------
constexpr int B_WT = 0;
constexpr int B_HO = 4352;
constexpr int B_C1 = 17152;
constexpr int B_TE = 17216;
constexpr int SMEM_B_BYTES = 17280 * 4;   // 69120

__global__ void __launch_bounds__(256, 3) kB(
    const float* __restrict__ mw1, const float* __restrict__ targ)
{
    extern __shared__ float smb[];
    float* wt  = smb + B_WT;
    float* hos = smb + B_HO;
    float* c1s = smb + B_C1;
    float* tes = smb + B_TE;

    const int tid = threadIdx.x;
    const int bid = blockIdx.x;          // 8192
    const int bh = bid >> 1, half = bid & 1;
    const int b = bh >> 2, h = bh & 3;

    if (tid < 64) tes[tid] = targ[b * 64 + tid];
    __syncthreads();

    const float* m1h = mw1 + (size_t)h * 32768 + (size_t)half * 64 * 256;
    for (int i = tid; i < 4096; i += 256) {
        int fl = i >> 6, d = i & 63;
        const float* r = m1h + fl * 256;
        wt[d * 68 + fl] = r[64 + d] - r[128 + d] + tes[d] * r[192 + d];
    }
    if (tid < 64) c1s[tid] = g_c1[(size_t)bh * 128 + half * 64 + tid];
    {
        const float4* hop = (const float4*)(g_ho + (size_t)bh * 12800);
        float4* hod = (float4*)hos;
        for (int i = tid; i < 3200; i += 256) hod[i] = hop[i];
    }
    __syncthreads();

    if (tid >= 200) return;
    const int t_tile = tid % 50, ftile = tid / 50;
    const int t0 = t_tile * 4;

    #pragma unroll
    for (int sub = 0; sub < 2; sub++) {
        const int fb = ftile * 16 + sub * 8;

        u64 acc[4][4];
        #pragma unroll
        for (int tt = 0; tt < 4; tt++)
            #pragma unroll
            for (int p = 0; p < 4; p++) acc[tt][p] = 0ull;

        #pragma unroll 4
        for (int d = 0; d < 64; d++) {
            float4 xv = *(const float4*)&hos[d * 200 + t0];
            u64 xt[4];
            xt[0] = pack2(xv.x, xv.x); xt[1] = pack2(xv.y, xv.y);
            xt[2] = pack2(xv.z, xv.z); xt[3] = pack2(xv.w, xv.w);
            const float* wr = &wt[d * 68 + fb];
            u64 wv[4];
            ld2x(wr,     wv[0], wv[1]);
            ld2x(wr + 4, wv[2], wv[3]);
            #pragma unroll
            for (int tt = 0; tt < 4; tt++)
                #pragma unroll
                for (int p = 0; p < 4; p++)
                    acc[tt][p] = fma2(xt[tt], wv[p], acc[tt][p]);
        }

        float* op = g_z1 + (size_t)bh * 25600 + (size_t)(half * 64 + fb) * 200 + t0;
        #pragma unroll
        for (int p = 0; p < 4; p++) {
            float e0, o0, e1, o1, e2, o2, e3, o3;
            unpack2(acc[0][p], e0, o0); unpack2(acc[1][p], e1, o1);
            unpack2(acc[2][p], e2, o2); unpack2(acc[3][p], e3, o3);
            float ce = c1s[fb + 2 * p], co = c1s[fb + 2 * p + 1];
            float4 ve = make_float4(e0 + ce, e1 + ce, e2 + ce, e3 + ce);
            float4 vo = make_float4(o0 + co, o1 + co, o2 + co, o3 + co);
            *(float4*)&op[(size_t)(2 * p) * 200] = ve;
            *(float4*)&op[(size_t)(2 * p + 1) * 200] = vo;
        }
    }
}

// ---------------- stats-1 (z1) ----------------
__global__ void __launch_bounds__(256) kP1()
{
    const int bid = blockIdx.x;          // 4096 blocks
    const int j = bid >> 3, sl = bid & 7;
    const int h = j >> 7, f = j & 127;
    const int tid = threadIdx.x;
    float sm = 0.f, sq = 0.f;
    if (tid < 200) {
        const size_t base = ((size_t)h * 128 + f) * 200 + tid;
        for (int b0 = sl * 128; b0 < sl * 128 + 128; b0 += 8) {
            float v0 = g_z1[base + (size_t)(b0 + 0) * 102400];
            float v1 = g_z1[base + (size_t)(b0 + 1) * 102400];
            float v2 = g_z1[base + (size_t)(b0 + 2) * 102400];
            float v3 = g_z1[base + (size_t)(b0 + 3) * 102400];
            float v4 = g_z1[base + (size_t)(b0 + 4) * 102400];
            float v5 = g_z1[base + (size_t)(b0 + 5) * 102400];
            float v6 = g_z1[base + (size_t)(b0 + 6) * 102400];
            float v7 = g_z1[base + (size_t)(b0 + 7) * 102400];
            sm += ((v0 + v1) + (v2 + v3)) + ((v4 + v5) + (v6 + v7));
            sq += fmaf(v0, v0, fmaf(v1, v1, fmaf(v2, v2, v3 * v3)))
                + fmaf(v4, v4, fmaf(v5, v5, fmaf(v6, v6, v7 * v7)));
        }
    }
    __shared__ double rs[256], rq[256];
    rs[tid] = (double)sm; rq[tid] = (double)sq;
    __syncthreads();
    for (int o = 128; o > 0; o >>= 1) {
        if (tid < o) { rs[tid] += rs[tid + o]; rq[tid] += rq[tid + o]; }
        __syncthreads();
    }
    if (tid == 0) { g_p1[bid * 2] = rs[0]; g_p1[bid * 2 + 1] = rq[0]; }
}

__global__ void __launch_bounds__(512) kFin1()
{
    const int j = threadIdx.x;   // 512
    double sm = 0.0, sq = 0.0;
    for (int sl = 0; sl < 8; sl++) {
        sm += g_p1[(j * 8 + sl) * 2];
        sq += g_p1[(j * 8 + sl) * 2 + 1];
    }
    double N = 204800.0;
    double mean = sm / N;
    double var = sq / N - mean * mean;
    if (var < 0.0) var = 0.0;
    g_mean1[j] = (float)mean;
    g_istd1[j] = (float)(1.0 / sqrt(var + 1e-9));
}

// ---------------- stats-2 finalize (partials written by kC epilogue) ----------------
__global__ void __launch_bounds__(256) kFin2()
{
    const int j = blockIdx.x;   // 256
    const int tid = threadIdx.x;
    double sm = 0.0, sq = 0.0;
    for (int b = tid; b < 1024; b += 256) {
        sm += (double)g_ps2s[j * 1024 + b];
        sq += (double)g_ps2q[j * 1024 + b];
    }
    __shared__ double rs[256], rq[256];
    rs[tid] = sm; rq[tid] = sq;
    __syncthreads();
    for (int o = 128; o > 0; o >>= 1) {
        if (tid < o) { rs[tid] += rs[tid + o]; rq[tid] += rq[tid + o]; }
        __syncthreads();
    }
    if (tid == 0) {
        double N = 204800.0;
        double mean = rs[0] / N;
        double var = rq[0] / N - mean * mean;
        if (var < 0.0) var = 0.0;
        g_mean2[j] = (float)mean;
        g_istd2[j] = (float)(1.0 / sqrt(var + 1e-9));
    }
}

// ---------------- kernel C: dice1 + mw2 GEMM, pipelined + fused stats-2 epilogue ----------------
constexpr int C_WS = 0;
constexpr int C_XS = 8192;        // two buffers of 6400
constexpr int C_MN = 20992;
constexpr int C_ISD = 21120;
constexpr int C_AL = 21248;
constexpr int C_MB = 21376;
constexpr int SMEM_C_BYTES = 21440 * 4;   // 85760

__global__ void __launch_bounds__(256, 2) kC(
    const float* __restrict__ mw2, const float* __restrict__ mb2,
    const float* __restrict__ alpha1)
{
    extern __shared__ float smc[];
    float* ws  = smc + C_WS;
    float* xs  = smc + C_XS;
    float* mn  = smc + C_MN;
    float* isd = smc + C_ISD;
    float* al  = smc + C_AL;
    float* mbs = smc + C_MB;

    const int tid = threadIdx.x, bh = blockIdx.x;
    const int b = bh >> 2, h = bh & 3;

    for (int i = tid; i < 8192; i += 256) {
        int f = i >> 6, g = i & 63;
        ws[i] = mw2[(size_t)h * 8192 + g * 128 + f];
    }
    if (tid < 128) {
        int j = h * 128 + tid;
        mn[tid] = g_mean1[j]; isd[tid] = g_istd1[j]; al[tid] = alpha1[j];
    } else if (tid < 192) {
        mbs[tid - 128] = mb2[h * 64 + (tid - 128)];
    }
    __syncthreads();   // mn/isd/al ready before dice

    const float* zbase = g_z1 + (size_t)bh * 25600;

    // prologue: stage phase 0 into buffer 0
    #pragma unroll
    for (int k = 0; k < 25; k++) {
        int i = tid + k * 256;
        int f = i / 200;
        float zv = zbase[i];
        float xa = (zv - mn[f]) * isd[f];
        float p = __fdividef(1.f, 1.f + __expf(-xa));
        xs[i] = (p + al[f] * (1.f - p)) * zv;
    }
    __syncthreads();

    const bool act = tid < 200;
    const int t_tile = tid % 50, g_tile = tid / 50;
    const int t0 = t_tile * 4, gb = (g_tile < 4 ? g_tile : 0) * 16;

    u64 acc[4][8];
    #pragma unroll
    for (int t = 0; t < 4; t++)
        #pragma unroll
        for (int p = 0; p < 8; p++) acc[t][p] = 0ull;

    float pre[25];

    for (int ft = 0; ft < 4; ft++) {
        if (ft < 3) {
            const float* zp = zbase + (ft + 1) * 6400;
            #pragma unroll
            for (int k = 0; k < 25; k++) pre[k] = zp[tid + k * 256];
        }
        const float* xcur = xs + (ft & 1) * 6400;
        if (act) {
            #pragma unroll 4
            for (int f = 0; f < 32; f++) {
                float4 xv = *(const float4*)&xcur[f * 200 + t0];
                u64 xt[4];
                xt[0] = pack2(xv.x, xv.x); xt[1] = pack2(xv.y, xv.y);
                xt[2] = pack2(xv.z, xv.z); xt[3] = pack2(xv.w, xv.w);
                const float* wr = &ws[(ft * 32 + f) * 64 + gb];
                u64 wv[8];
                ld2x(wr,      wv[0], wv[1]);
                ld2x(wr + 4,  wv[2], wv[3]);
                ld2x(wr + 8,  wv[4], wv[5]);
                ld2x(wr + 12, wv[6], wv[7]);
                #pragma unroll
                for (int t = 0; t < 4; t++)
                    #pragma unroll
                    for (int p = 0; p < 8; p++)
                        acc[t][p] = fma2(xt[t], wv[p], acc[t][p]);
            }
        }
        if (ft < 3) {
            __syncthreads();
            float* xn = xs + ((ft + 1) & 1) * 6400;
            const int fbase = (ft + 1) * 32;
            #pragma unroll
            for (int k = 0; k < 25; k++) {
                int i = tid + k * 256;
                int fg = fbase + i / 200;
                float zv = pre[k];
                float xa = (zv - mn[fg]) * isd[fg];
                float p = __fdividef(1.f, 1.f + __expf(-xa));
                xn[i] = (p + al[fg] * (1.f - p)) * zv;
            }
            __syncthreads();
        }
    }

    // all ws reads done (last in ft=3 compute) -> reuse ws for stats partials
    __syncthreads();
    float* ps = ws;            // [g*50 + t_tile] per-thread sums
    float* pq = ws + 3200;

    if (act) {
        float* op = g_z2 + (size_t)bh * 12800 + t0;
        #pragma unroll
        for (int p = 0; p < 8; p++) {
            float e0, o0, e1, o1, e2, o2, e3, o3;
            unpack2(acc[0][p], e0, o0); unpack2(acc[1][p], e1, o1);
            unpack2(acc[2][p], e2, o2); unpack2(acc[3][p], e3, o3);
            int ge = gb + 2 * p, go = ge + 1;
            float be = mbs[ge], bo = mbs[go];
            float4 ve = make_float4(e0 + be, e1 + be, e2 + be, e3 + be);
            float4 vo = make_float4(o0 + bo, o1 + bo, o2 + bo, o3 + bo);
            *(float4*)&op[(size_t)ge * 200] = ve;
            *(float4*)&op[(size_t)go * 200] = vo;
            // stats partials (deterministic order)
            ps[ge * 50 + t_tile] = ((ve.x + ve.y) + (ve.z + ve.w));
            pq[ge * 50 + t_tile] = fmaf(ve.x, ve.x, fmaf(ve.y, ve.y, fmaf(ve.z, ve.z, ve.w * ve.w)));
            ps[go * 50 + t_tile] = ((vo.x + vo.y) + (vo.z + vo.w));
            pq[go * 50 + t_tile] = fmaf(vo.x, vo.x, fmaf(vo.y, vo.y, fmaf(vo.z, vo.z, vo.w * vo.w)));
        }
    }
    __syncthreads();

    if (tid < 64) {
        float sm = 0.f, sq = 0.f;
        const float* pr = &ps[tid * 50];
        const float* qr = &pq[tid * 50];
        #pragma unroll 5
        for (int i = 0; i < 50; i++) { sm += pr[i]; sq += qr[i]; }
        int j = h * 64 + tid;
        g_ps2s[j * 1024 + b] = sm;
        g_ps2q[j * 1024 + b] = sq;
    }
}

// ---------------- kernel E: dice2 + score + softmax + pooling ----------------
__global__ void __launch_bounds__(256) kE(
    const int* __restrict__ mask, const float* __restrict__ mw3,
    const float* __restrict__ mb3, const float* __restrict__ alpha2,
    float* __restrict__ out)
{
    __shared__ float w3s[64], m2s[64], i2s[64], a2s[64];
    __shared__ float red[256];
    __shared__ float wts[200];
    const int tid = threadIdx.x, bid = blockIdx.x;
    const int b = bid >> 2, h = bid & 3;
    if (tid < 64) {
        int j = h * 64 + tid;
        w3s[tid] = mw3[j]; m2s[tid] = g_mean2[j]; i2s[tid] = g_istd2[j]; a2s[tid] = alpha2[j];
    }
    __syncthreads();

    float sc = -3.0e38f;
    if (tid < 200) {
        const float* zp = g_z2 + (size_t)bid * 12800 + tid;
        float a = 0.f;
        #pragma unroll 4
        for (int g = 0; g < 64; g++) {
            float zv = zp[g * 200];
            float xa = (zv - m2s[g]) * i2s[g];
            float p = __fdividef(1.f, 1.f + __expf(-xa));
            float xv = (p + a2s[g] * (1.f - p)) * zv;
            a = fmaf(xv, w3s[g], a);
        }
        sc = a + mb3[h];
        if (mask[b * 200 + tid] == 0) sc = -1e9f;
    }
    red[tid] = sc;
    __syncthreads();
    for (int o = 128; o > 0; o >>= 1) {
        if (tid < o) red[tid] = fmaxf(red[tid], red[tid + o]);
        __syncthreads();
    }
    float mx = red[0];
    __syncthreads();
    float e = (tid < 200) ? __expf(sc - mx) : 0.f;
    red[tid] = e;
    __syncthreads();
    for (int o = 128; o > 0; o >>= 1) {
        if (tid < o) red[tid] += red[tid + o];
        __syncthreads();
    }
    float inv = 1.f / red[0];
    if (tid < 200) wts[tid] = e * inv;
    __syncthreads();

    const int c = tid >> 6, d = tid & 63;
    const float* hp = g_ho + (size_t)bid * 12800 + d * 200 + c * 50;
    float acc = 0.f;
    #pragma unroll 2
    for (int i = 0; i < 50; i++)
        acc = fmaf(wts[c * 50 + i], hp[i], acc);
    red[tid] = acc;
    __syncthreads();
    if (tid < 64)
        out[(size_t)bid * 64 + tid] = (red[tid] + red[tid + 64]) + (red[tid + 128] + red[tid + 192]);
}

// ---------------- launch ----------------
extern "C" void kernel_launch(void* const* d_in, const int* in_sizes, int n_in,
                              void* d_out, int out_size)
{
    const float* seq  = (const float*)d_in[0];
    const float* targ = (const float*)d_in[1];
    const int*   mask = (const int*)d_in[2];
    const float* Wqkv = (const float*)d_in[3];
    const float* Wo   = (const float*)d_in[4];
    const float* lng  = (const float*)d_in[5];
    const float* lnb  = (const float*)d_in[6];
    const float* fw1  = (const float*)d_in[7];
    const float* fb1  = (const float*)d_in[8];
    const float* fw2  = (const float*)d_in[9];
    const float* fb2  = (const float*)d_in[10];
    const float* mw1  = (const float*)d_in[11];
    const float* mb1  = (const float*)d_in[12];
    const float* a1   = (const float*)d_in[13];
    const float* mw2  = (const float*)d_in[14];
    const float* mb2  = (const float*)d_in[15];
    const float* a2   = (const float*)d_in[16];
    const float* mw3  = (const float*)d_in[17];
    const float* mb3  = (const float*)d_in[18];
    float* out = (float*)d_out;

    cudaFuncSetAttribute(kA, cudaFuncAttributeMaxDynamicSharedMemorySize, SMEM_A_BYTES);
    cudaFuncSetAttribute(kB, cudaFuncAttributeMaxDynamicSharedMemorySize, SMEM_B_BYTES);
    cudaFuncSetAttribute(kC, cudaFuncAttributeMaxDynamicSharedMemorySize, SMEM_C_BYTES);

    kW<<<64, 256>>>(fw2);
    kB0<<<4096, 128>>>(mw1, mb1, targ);
    kA<<<4096, 224, SMEM_A_BYTES>>>(seq, Wqkv, Wo, lng, lnb, fw1, fb1, fb2);
    kB<<<8192, 256, SMEM_B_BYTES>>>(mw1, targ);
    kP1<<<4096, 256>>>();
    kFin1<<<1, 512>>>();
    kC<<<4096, 256, SMEM_C_BYTES>>>(mw2, mb2, a1);
    kFin2<<<256, 256>>>();
    kE<<<4096, 256>>>(mask, mw3, mb3, a2, out);
}

// round 17
// speedup vs baseline: 1.0520x; 1.0028x over previous
#include <cuda_runtime.h>
#include <math.h>

typedef unsigned long long u64;

// ---------------- f32x2 packed helpers ----------------
__device__ __forceinline__ u64 fma2(u64 a, u64 b, u64 c) {
    u64 d; asm("fma.rn.f32x2 %0, %1, %2, %3;" : "=l"(d) : "l"(a), "l"(b), "l"(c)); return d;
}
__device__ __forceinline__ u64 pack2(float x, float y) {
    u64 r; asm("mov.b64 %0, {%1, %2};" : "=l"(r) : "f"(x), "f"(y)); return r;
}
__device__ __forceinline__ float hsum2(u64 v) {
    float a, b; asm("mov.b64 {%0, %1}, %2;" : "=f"(a), "=f"(b) : "l"(v)); return a + b;
}
__device__ __forceinline__ void unpack2(u64 v, float& a, float& b) {
    asm("mov.b64 {%0, %1}, %2;" : "=f"(a), "=f"(b) : "l"(v));
}
union F4U { float4 f; u64 u[2]; };
__device__ __forceinline__ void ld2x(const float* p, u64& a, u64& b) {
    F4U t; t.f = *(const float4*)p; a = t.u[0]; b = t.u[1];
}

// ---------------- scratch (no allocs allowed) ----------------
__device__ float g_ho[52428800];    // (b,h,d,t)  210 MB
__device__ float g_z1[104857600];   // (b,h,f,t)  419 MB
__device__ float g_z2[52428800];    // (b,h,g,t)  210 MB
__device__ float g_c1[524288];      // (b,h,f)    2 MB
__device__ float g_w2t[16384];      // transposed ffn_w2 [h][f][j]
__device__ double g_p1[4096 * 2];
__device__ float g_ps2s[262144];    // stats2 partials: [j=256][b=1024]
__device__ float g_ps2q[262144];
__device__ float g_mean1[512], g_istd1[512];
__device__ float g_mean2[256], g_istd2[256];

// ---------------- kernel W: one-shot transpose of ffn_w2 ----------------
__global__ void __launch_bounds__(256) kW(const float* __restrict__ fw2)
{
    int i = blockIdx.x * 256 + threadIdx.x;     // 16384
    int h = i >> 12, r = i & 4095;
    int f = r >> 6, j = r & 63;
    g_w2t[i] = fw2[h * 4096 + j * 64 + f];
}

// ---------------- kernel A: QKV + attention + W_o/LN + FFN -> ho ----------------
constexpr int OFF_KK = 0;
constexpr int OFF_VV = 4000;
constexpr int OFF_WO = 8000;
constexpr int OFF_R1 = 9024;
constexpr int OFF_LNG = 17216;
constexpr int OFF_LNB = 17280;
constexpr int OFF_B1 = 17344;
constexpr int OFF_B2 = 17408;
constexpr int SMEM_A_FLOATS = 17472;
constexpr int SMEM_A_BYTES = SMEM_A_FLOATS * 4;   // 69888

__global__ void __launch_bounds__(256, 2) kA(
    const float* __restrict__ seq,
    const float* __restrict__ Wqkv, const float* __restrict__ Wo,
    const float* __restrict__ lng, const float* __restrict__ lnb,
    const float* __restrict__ fw1, const float* __restrict__ fb1,
    const float* __restrict__ fb2)
{
    extern __shared__ float sm[];
    float* kk  = sm + OFF_KK;
    float* vv  = sm + OFF_VV;
    float* wo  = sm + OFF_WO;
    float* R1  = sm + OFF_R1;
    float* lngs = sm + OFF_LNG;
    float* lnbs = sm + OFF_LNB;
    float* b1s = sm + OFF_B1;
    float* b2s = sm + OFF_B2;
    float* h1s = sm;               // reuse kk/vv post-attention (6400 <= 8000)

    const int tid = threadIdx.x;
    const int bid = blockIdx.x;
    const int b = bid >> 2, h = bid & 3;

    // ---- phase-1 loads: qkv weights + wo + vectors ----
    for (int i = tid; i < 1024; i += 256) {
        int r = i >> 6, d = i & 63;
        R1[i]        = Wqkv[(h * 16 + r) * 64 + d];
        R1[1024 + i] = Wqkv[(64 + h * 16 + r) * 64 + d];
        R1[2048 + i] = Wqkv[(128 + h * 16 + r) * 64 + d];
        wo[i] = Wo[h * 1024 + i];
    }
    if (tid < 64) {
        lngs[tid] = lng[h * 64 + tid];
        lnbs[tid] = lnb[h * 64 + tid];
        b1s[tid]  = fb1[h * 64 + tid];
        b2s[tid]  = fb2[h * 64 + tid];
    }
    __syncthreads();

    const bool act = tid < 200;
    const int t = act ? tid : 0;
    const int t20 = t * 20;

    // ---- QKV: thread = token; q -> regs, k/v -> smem ----
    u64 qp[8];
    if (act) {
        u64 xp[32];
        const float* xr = seq + (size_t)b * 12800 + t * 64;
        #pragma unroll
        for (int j4 = 0; j4 < 16; j4++) ld2x(xr + j4 * 4, xp[2 * j4], xp[2 * j4 + 1]);
        float qv[16];
        #pragma unroll 4
        for (int i = 0; i < 16; i++) {
            u64 q0 = 0, q1 = 0, k0 = 0, k1 = 0, v0 = 0, v1 = 0, wa, wb;
            #pragma unroll
            for (int j4 = 0; j4 < 16; j4++) {
                ld2x(R1 + i * 64 + j4 * 4, wa, wb);
                q0 = fma2(xp[2 * j4], wa, q0); q1 = fma2(xp[2 * j4 + 1], wb, q1);
                ld2x(R1 + 1024 + i * 64 + j4 * 4, wa, wb);
                k0 = fma2(xp[2 * j4], wa, k0); k1 = fma2(xp[2 * j4 + 1], wb, k1);
                ld2x(R1 + 2048 + i * 64 + j4 * 4, wa, wb);
                v0 = fma2(xp[2 * j4], wa, v0); v1 = fma2(xp[2 * j4 + 1], wb, v1);
            }
            qv[i] = hsum2(q0) + hsum2(q1);
            kk[t20 + i] = hsum2(k0) + hsum2(k1);
            vv[t20 + i] = hsum2(v0) + hsum2(v1);
        }
        #pragma unroll
        for (int ip = 0; ip < 8; ip++) qp[ip] = pack2(qv[2 * ip], qv[2 * ip + 1]);
    }
    __syncthreads();   // QKV done; R1 free for w1/w2t

    // ---- phase-2 loads: w1 | w2t into R1 (both coalesced) ----
    for (int i = tid; i < 4096; i += 256) {
        R1[i] = fw1[h * 4096 + i];
        R1[4096 + i] = g_w2t[h * 4096 + i];
    }
    __syncthreads();
    float* w1 = R1;
    float* w2t = R1 + 4096;

    u64 sp[32];        // s row -> srg -> ho
    u64 h1b[16];       // h1 second half
    const u64 one2 = pack2(1.f, 1.f);

    if (act) {
        // ---- attention, 4-way interleaved (exp without max: scores bounded) ----
        u64 ctx[8];
        #pragma unroll
        for (int r = 0; r < 8; r++) ctx[r] = 0ull;
        float l = 0.f;
        for (int t2 = 0; t2 < 200; t2 += 4) {
            const float* kr0 = &kk[t2 * 20];
            const float* kr1 = kr0 + 20;
            const float* kr2 = kr0 + 40;
            const float* kr3 = kr0 + 60;
            u64 dA0 = 0, dA1 = 0, dB0 = 0, dB1 = 0;
            u64 dC0 = 0, dC1 = 0, dD0 = 0, dD1 = 0;
            u64 ka, kb;
            ld2x(kr0,      ka, kb); dA0 = fma2(qp[0], ka, dA0); dA1 = fma2(qp[1], kb, dA1);
            ld2x(kr1,      ka, kb); dB0 = fma2(qp[0], ka, dB0); dB1 = fma2(qp[1], kb, dB1);
            ld2x(kr2,      ka, kb); dC0 = fma2(qp[0], ka, dC0); dC1 = fma2(qp[1], kb, dC1);
            ld2x(kr3,      ka, kb); dD0 = fma2(qp[0], ka, dD0); dD1 = fma2(qp[1], kb, dD1);
            ld2x(kr0 + 4,  ka, kb); dA0 = fma2(qp[2], ka, dA0); dA1 = fma2(qp[3], kb, dA1);
            ld2x(kr1 + 4,  ka, kb); dB0 = fma2(qp[2], ka, dB0); dB1 = fma2(qp[3], kb, dB1);
            ld2x(kr2 + 4,  ka, kb); dC0 = fma2(qp[2], ka, dC0); dC1 = fma2(qp[3], kb, dC1);
            ld2x(kr3 + 4,  ka, kb); dD0 = fma2(qp[2], ka, dD0); dD1 = fma2(qp[3], kb, dD1);
            ld2x(kr0 + 8,  ka, kb); dA0 = fma2(qp[4], ka, dA0); dA1 = fma2(qp[5], kb, dA1);
            ld2x(kr1 + 8,  ka, kb); dB0 = fma2(qp[4], ka, dB0); dB1 = fma2(qp[5], kb, dB1);
            ld2x(kr2 + 8,  ka, kb); dC0 = fma2(qp[4], ka, dC0); dC1 = fma2(qp[5], kb, dC1);
            ld2x(kr3 + 8,  ka, kb); dD0 = fma2(qp[4], ka, dD0); dD1 = fma2(qp[5], kb, dD1);
            ld2x(kr0 + 12, ka, kb); dA0 = fma2(qp[6], ka, dA0); dA1 = fma2(qp[7], kb, dA1);
            ld2x(kr1 + 12, ka, kb); dB0 = fma2(qp[6], ka, dB0); dB1 = fma2(qp[7], kb, dB1);
            ld2x(kr2 + 12, ka, kb); dC0 = fma2(qp[6], ka, dC0); dC1 = fma2(qp[7], kb, dC1);
            ld2x(kr3 + 12, ka, kb); dD0 = fma2(qp[6], ka, dD0); dD1 = fma2(qp[7], kb, dD1);
            float p0 = __expf((hsum2(dA0) + hsum2(dA1)) * 0.25f);
            float p1 = __expf((hsum2(dB0) + hsum2(dB1)) * 0.25f);
            float p2 = __expf((hsum2(dC0) + hsum2(dC1)) * 0.25f);
            float p3 = __expf((hsum2(dD0) + hsum2(dD1)) * 0.25f);
            l += (p0 + p1) + (p2 + p3);
            u64 pp0 = pack2(p0, p0), pp1 = pack2(p1, p1);
            u64 pp2 = pack2(p2, p2), pp3 = pack2(p3, p3);
            const float* vr0 = &vv[t2 * 20];
            const float* vr1 = vr0 + 20;
            const float* vr2 = vr0 + 40;
            const float* vr3 = vr0 + 60;
            u64 va, vb;
            ld2x(vr0,      va, vb); ctx[0] = fma2(pp0, va, ctx[0]); ctx[1] = fma2(pp0, vb, ctx[1]);
            ld2x(vr1,      va, vb); ctx[0] = fma2(pp1, va, ctx[0]); ctx[1] = fma2(pp1, vb, ctx[1]);
            ld2x(vr2,      va, vb); ctx[0] = fma2(pp2, va, ctx[0]); ctx[1] = fma2(pp2, vb, ctx[1]);
            ld2x(vr3,      va, vb); ctx[0] = fma2(pp3, va, ctx[0]); ctx[1] = fma2(pp3, vb, ctx[1]);
            ld2x(vr0 + 4,  va, vb); ctx[2] = fma2(pp0, va, ctx[2]); ctx[3] = fma2(pp0, vb, ctx[3]);
            ld2x(vr1 + 4,  va, vb); ctx[2] = fma2(pp1, va, ctx[2]); ctx[3] = fma2(pp1, vb, ctx[3]);
            ld2x(vr2 + 4,  va, vb); ctx[2] = fma2(pp2, va, ctx[2]); ctx[3] = fma2(pp2, vb, ctx[3]);
            ld2x(vr3 + 4,  va, vb); ctx[2] = fma2(pp3, va, ctx[2]); ctx[3] = fma2(pp3, vb, ctx[3]);
            ld2x(vr0 + 8,  va, vb); ctx[4] = fma2(pp0, va, ctx[4]); ctx[5] = fma2(pp0, vb, ctx[5]);
            ld2x(vr1 + 8,  va, vb); ctx[4] = fma2(pp1, va, ctx[4]); ctx[5] = fma2(pp1, vb, ctx[5]);
            ld2x(vr2 + 8,  va, vb); ctx[4] = fma2(pp2, va, ctx[4]); ctx[5] = fma2(pp2, vb, ctx[5]);
            ld2x(vr3 + 8,  va, vb); ctx[4] = fma2(pp3, va, ctx[4]); ctx[5] = fma2(pp3, vb, ctx[5]);
            ld2x(vr0 + 12, va, vb); ctx[6] = fma2(pp0, va, ctx[6]); ctx[7] = fma2(pp0, vb, ctx[7]);
            ld2x(vr1 + 12, va, vb); ctx[6] = fma2(pp1, va, ctx[6]); ctx[7] = fma2(pp1, vb, ctx[7]);
            ld2x(vr2 + 12, va, vb); ctx[6] = fma2(pp2, va, ctx[6]); ctx[7] = fma2(pp2, vb, ctx[7]);
            ld2x(vr3 + 12, va, vb); ctx[6] = fma2(pp3, va, ctx[6]); ctx[7] = fma2(pp3, vb, ctx[7]);
        }
        {
            float rl = 1.f / l;
            u64 rl2 = pack2(rl, rl);
            #pragma unroll
            for (int r = 0; r < 8; r++) ctx[r] = fma2(ctx[r], rl2, 0ull);
        }

        // ---- W_o + residual (x streamed from gmem), LN stats ----
        const float* xr = seq + (size_t)b * 12800 + t * 64;
        u64 mu2 = 0ull, q22 = 0ull;
        #pragma unroll 2
        for (int jp = 0; jp < 32; jp++) {
            const float* wr0 = &wo[(2 * jp) * 16];
            const float* wr1 = wr0 + 16;
            u64 a0 = 0, a1 = 0, b0 = 0, b1 = 0, wa, wb;
            ld2x(wr0,      wa, wb); a0 = fma2(ctx[0], wa, a0); a1 = fma2(ctx[1], wb, a1);
            ld2x(wr0 + 4,  wa, wb); a0 = fma2(ctx[2], wa, a0); a1 = fma2(ctx[3], wb, a1);
            ld2x(wr0 + 8,  wa, wb); a0 = fma2(ctx[4], wa, a0); a1 = fma2(ctx[5], wb, a1);
            ld2x(wr0 + 12, wa, wb); a0 = fma2(ctx[6], wa, a0); a1 = fma2(ctx[7], wb, a1);
            ld2x(wr1,      wa, wb); b0 = fma2(ctx[0], wa, b0); b1 = fma2(ctx[1], wb, b1);
            ld2x(wr1 + 4,  wa, wb); b0 = fma2(ctx[2], wa, b0); b1 = fma2(ctx[3], wb, b1);
            ld2x(wr1 + 8,  wa, wb); b0 = fma2(ctx[4], wa, b0); b1 = fma2(ctx[5], wb, b1);
            ld2x(wr1 + 12, wa, wb); b0 = fma2(ctx[6], wa, b0); b1 = fma2(ctx[7], wb, b1);
            float2 xv = *(const float2*)(xr + 2 * jp);
            float s0 = hsum2(a0) + hsum2(a1) + xv.x;
            float s1 = hsum2(b0) + hsum2(b1) + xv.y;
            u64 spp = pack2(s0, s1);
            sp[jp] = spp;
            mu2 = fma2(spp, one2, mu2);
            q22 = fma2(spp, spp, q22);
        }
        float mu = hsum2(mu2) * (1.f / 64.f);
        float var = hsum2(q22) * (1.f / 64.f) - mu * mu;
        float rstd = rsqrtf(var + 1e-5f);

        // ---- LN in place: sp := srg ----
        {
            u64 rstd2 = pack2(rstd, rstd);
            float nm = -mu * rstd;
            u64 nmr = pack2(nm, nm);
            #pragma unroll
            for (int j4 = 0; j4 < 16; j4++) {
                u64 ga, gb, ba, bb;
                ld2x(&lngs[j4 * 4], ga, gb);
                ld2x(&lnbs[j4 * 4], ba, bb);
                sp[2 * j4]     = fma2(fma2(sp[2 * j4],     rstd2, nmr), ga, ba);
                sp[2 * j4 + 1] = fma2(fma2(sp[2 * j4 + 1], rstd2, nmr), gb, bb);
            }
        }
    }

    __syncthreads();   // all warps past attention: kk/vv region free -> h1s

    if (!act) return;

    // ---- FFN pass1a: f = 0..31 -> h1s (smem) ----
    #pragma unroll 2
    for (int f = 0; f < 32; f++) {
        const float* w1r = &w1[f * 64];
        u64 a0 = 0, a1 = 0, a2 = 0, a3 = 0, wa, wb;
        #pragma unroll
        for (int j4 = 0; j4 < 16; j4 += 2) {
            ld2x(&w1r[j4 * 4], wa, wb);
            a0 = fma2(sp[2 * j4], wa, a0); a1 = fma2(sp[2 * j4 + 1], wb, a1);
            ld2x(&w1r[j4 * 4 + 4], wa, wb);
            a2 = fma2(sp[2 * j4 + 2], wa, a2); a3 = fma2(sp[2 * j4 + 3], wb, a3);
        }
        h1s[f * 200 + t] = fmaxf((hsum2(a0) + hsum2(a1)) + (hsum2(a2) + hsum2(a3)) + b1s[f], 0.f);
    }

    // ---- FFN pass1b: f = 32..63 -> regs ----
    #pragma unroll 2
    for (int fp = 0; fp < 16; fp++) {
        const float* w0 = &w1[(32 + 2 * fp) * 64];
        const float* wB = w0 + 64;
        u64 a0 = 0, a1 = 0, b0 = 0, b1 = 0, wa, wb;
        #pragma unroll
        for (int j4 = 0; j4 < 16; j4++) {
            ld2x(&w0[j4 * 4], wa, wb);
            a0 = fma2(sp[2 * j4], wa, a0); a1 = fma2(sp[2 * j4 + 1], wb, a1);
            ld2x(&wB[j4 * 4], wa, wb);
            b0 = fma2(sp[2 * j4], wa, b0); b1 = fma2(sp[2 * j4 + 1], wb, b1);
        }
        float hA = fmaxf(hsum2(a0) + hsum2(a1) + b1s[32 + 2 * fp], 0.f);
        float hB = fmaxf(hsum2(b0) + hsum2(b1) + b1s[33 + 2 * fp], 0.f);
        h1b[fp] = pack2(hA, hB);
    }

    // ---- sp := srg + b2 (ho accumulator) ----
    #pragma unroll
    for (int j4 = 0; j4 < 16; j4++) {
        u64 ca, cb;
        ld2x(&b2s[j4 * 4], ca, cb);
        sp[2 * j4]     = fma2(sp[2 * j4],     one2, ca);
        sp[2 * j4 + 1] = fma2(sp[2 * j4 + 1], one2, cb);
    }

    // ---- FFN pass2b: consume h1b (f = 32..63) ----
    #pragma unroll 2
    for (int fp = 0; fp < 16; fp++) {
        float hA, hB;
        unpack2(h1b[fp], hA, hB);
        u64 hA2 = pack2(hA, hA), hB2 = pack2(hB, hB);
        const float* r0 = &w2t[(32 + 2 * fp) * 64];
        const float* r1 = r0 + 64;
        u64 wa, wb;
        #pragma unroll
        for (int j4 = 0; j4 < 16; j4++) {
            ld2x(&r0[j4 * 4], wa, wb);
            sp[2 * j4]     = fma2(hA2, wa, sp[2 * j4]);
            sp[2 * j4 + 1] = fma2(hA2, wb, sp[2 * j4 + 1]);
        }
        #pragma unroll
        for (int j4 = 0; j4 < 16; j4++) {
            ld2x(&r1[j4 * 4], wa, wb);
            sp[2 * j4]     = fma2(hB2, wa, sp[2 * j4]);
            sp[2 * j4 + 1] = fma2(hB2, wb, sp[2 * j4 + 1]);
        }
    }

    // ---- FFN pass2a: consume h1s (f = 0..31) ----
    #pragma unroll 2
    for (int f = 0; f < 32; f++) {
        float hf = h1s[f * 200 + t];
        u64 hf2 = pack2(hf, hf);
        const float* r0 = &w2t[f * 64];
        u64 wa, wb;
        #pragma unroll
        for (int j4 = 0; j4 < 16; j4++) {
            ld2x(&r0[j4 * 4], wa, wb);
            sp[2 * j4]     = fma2(hf2, wa, sp[2 * j4]);
            sp[2 * j4 + 1] = fma2(hf2, wb, sp[2 * j4 + 1]);
        }
    }

    // ---- store ho in (d,t) layout (coalesced) ----
    float* hop = g_ho + (size_t)bid * 12800 + t;
    #pragma unroll
    for (int jp = 0; jp < 32; jp++) {
        float a, c;
        unpack2(sp[jp], a, c);
        hop[(2 * jp) * 200] = a;
        hop[(2 * jp + 1) * 200] = c;
    }
}

// ---------------- kernel B0: c1[b,h,f] = mb1 + (W1+W3) te  (coalesced) ----------------
__global__ void __launch_bounds__(128) kB0(
    const float* __restrict__ mw1, const float* __restrict__ mb1,
    const float* __restrict__ targ)
{
    __shared__ float msum[128 * 65];
    __shared__ float tes[64];
    const int tid = threadIdx.x;
    const int bid = blockIdx.x;        // 4096 = (b,h)
    const int b = bid >> 2, h = bid & 3;
    if (tid < 64) tes[tid] = targ[b * 64 + tid];
    const float* m1h = mw1 + (size_t)h * 32768;
    for (int i = tid; i < 8192; i += 128) {
        int f = i >> 6, d = i & 63;     // d fastest -> coalesced
        msum[f * 65 + d] = m1h[f * 256 + d] + m1h[f * 256 + 128 + d];
    }
    __syncthreads();
    float a = mb1[h * 128 + tid];
    const float* mr = &msum[tid * 65];
    #pragma unroll 8
    for (int d = 0; d < 64; d++) a = fmaf(mr[d], tes[d], a);
    g_c1[(size_t)bid * 128 + tid] = a;
}

// ---------------- kernel B: z1 = Weff(b,h) @ ho, two 4t x 8f register-tile passes ----------------
constexpr int B_WT = 0;
constexpr int B_HO = 4352;
constexpr int B_C1 = 17152;
constexpr int B_TE = 17216;
constexpr int SMEM_B_BYTES = 17280 * 4;   // 69120

__global__ void __launch_bounds__(256, 3) kB(
    const float* __restrict__ mw1, const float* __restrict__ targ)
{
    extern __shared__ float smb[];
    float* wt  = smb + B_WT;
    float* hos = smb + B_HO;
    float* c1s = smb + B_C1;
    float* tes = smb + B_TE;

    const int tid = threadIdx.x;
    const int bid = blockIdx.x;          // 8192
    const int bh = bid >> 1, half = bid & 1;
    const int b = bh >> 2, h = bh & 3;

    if (tid < 64) tes[tid] = targ[b * 64 + tid];
    __syncthreads();

    const float* m1h = mw1 + (size_t)h * 32768 + (size_t)half * 64 * 256;
    for (int i = tid; i < 4096; i += 256) {
        int fl = i >> 6, d = i & 63;
        const float* r = m1h + fl * 256;
        wt[d * 68 + fl] = r[64 + d] - r[128 + d] + tes[d] * r[192 + d];
    }
    if (tid < 64) c1s[tid] = g_c1[(size_t)bh * 128 + half * 64 + tid];
    {
        const float4* hop = (const float4*)(g_ho + (size_t)bh * 12800);
        float4* hod = (float4*)hos;
        for (int i = tid; i < 3200; i += 256) hod[i] = hop[i];
    }
    __syncthreads();

    if (tid >= 200) return;
    const int t_tile = tid % 50, ftile = tid / 50;
    const int t0 = t_tile * 4;

    #pragma unroll
    for (int sub = 0; sub < 2; sub++) {
        const int fb = ftile * 16 + sub * 8;

        u64 acc[4][4];
        #pragma unroll
        for (int tt = 0; tt < 4; tt++)
            #pragma unroll
            for (int p = 0; p < 4; p++) acc[tt][p] = 0ull;

        #pragma unroll 4
        for (int d = 0; d < 64; d++) {
            float4 xv = *(const float4*)&hos[d * 200 + t0];
            u64 xt[4];
            xt[0] = pack2(xv.x, xv.x); xt[1] = pack2(xv.y, xv.y);
            xt[2] = pack2(xv.z, xv.z); xt[3] = pack2(xv.w, xv.w);
            const float* wr = &wt[d * 68 + fb];
            u64 wv[4];
            ld2x(wr,     wv[0], wv[1]);
            ld2x(wr + 4, wv[2], wv[3]);
            #pragma unroll
            for (int tt = 0; tt < 4; tt++)
                #pragma unroll
                for (int p = 0; p < 4; p++)
                    acc[tt][p] = fma2(xt[tt], wv[p], acc[tt][p]);
        }

        float* op = g_z1 + (size_t)bh * 25600 + (size_t)(half * 64 + fb) * 200 + t0;
        #pragma unroll
        for (int p = 0; p < 4; p++) {
            float e0, o0, e1, o1, e2, o2, e3, o3;
            unpack2(acc[0][p], e0, o0); unpack2(acc[1][p], e1, o1);
            unpack2(acc[2][p], e2, o2); unpack2(acc[3][p], e3, o3);
            float ce = c1s[fb + 2 * p], co = c1s[fb + 2 * p + 1];
            float4 ve = make_float4(e0 + ce, e1 + ce, e2 + ce, e3 + ce);
            float4 vo = make_float4(o0 + co, o1 + co, o2 + co, o3 + co);
            *(float4*)&op[(size_t)(2 * p) * 200] = ve;
            *(float4*)&op[(size_t)(2 * p + 1) * 200] = vo;
        }
    }
}

// ---------------- stats-1 (z1) ----------------
__global__ void __launch_bounds__(256) kP1()
{
    const int bid = blockIdx.x;          // 4096 blocks
    const int j = bid >> 3, sl = bid & 7;
    const int h = j >> 7, f = j & 127;
    const int tid = threadIdx.x;
    float sm = 0.f, sq = 0.f;
    if (tid < 200) {
        const size_t base = ((size_t)h * 128 + f) * 200 + tid;
        for (int b0 = sl * 128; b0 < sl * 128 + 128; b0 += 8) {
            float v0 = g_z1[base + (size_t)(b0 + 0) * 102400];
            float v1 = g_z1[base + (size_t)(b0 + 1) * 102400];
            float v2 = g_z1[base + (size_t)(b0 + 2) * 102400];
            float v3 = g_z1[base + (size_t)(b0 + 3) * 102400];
            float v4 = g_z1[base + (size_t)(b0 + 4) * 102400];
            float v5 = g_z1[base + (size_t)(b0 + 5) * 102400];
            float v6 = g_z1[base + (size_t)(b0 + 6) * 102400];
            float v7 = g_z1[base + (size_t)(b0 + 7) * 102400];
            sm += ((v0 + v1) + (v2 + v3)) + ((v4 + v5) + (v6 + v7));
            sq += fmaf(v0, v0, fmaf(v1, v1, fmaf(v2, v2, v3 * v3)))
                + fmaf(v4, v4, fmaf(v5, v5, fmaf(v6, v6, v7 * v7)));
        }
    }
    __shared__ double rs[256], rq[256];
    rs[tid] = (double)sm; rq[tid] = (double)sq;
    __syncthreads();
    for (int o = 128; o > 0; o >>= 1) {
        if (tid < o) { rs[tid] += rs[tid + o]; rq[tid] += rq[tid + o]; }
        __syncthreads();
    }
    if (tid == 0) { g_p1[bid * 2] = rs[0]; g_p1[bid * 2 + 1] = rq[0]; }
}

__global__ void __launch_bounds__(512) kFin1()
{
    const int j = threadIdx.x;   // 512
    double sm = 0.0, sq = 0.0;
    for (int sl = 0; sl < 8; sl++) {
        sm += g_p1[(j * 8 + sl) * 2];
        sq += g_p1[(j * 8 + sl) * 2 + 1];
    }
    double N = 204800.0;
    double mean = sm / N;
    double var = sq / N - mean * mean;
    if (var < 0.0) var = 0.0;
    g_mean1[j] = (float)mean;
    g_istd1[j] = (float)(1.0 / sqrt(var + 1e-9));
}

// ---------------- stats-2 finalize (partials written by kC epilogue) ----------------
__global__ void __launch_bounds__(256) kFin2()
{
    const int j = blockIdx.x;   // 256
    const int tid = threadIdx.x;
    double sm = 0.0, sq = 0.0;
    for (int b = tid; b < 1024; b += 256) {
        sm += (double)g_ps2s[j * 1024 + b];
        sq += (double)g_ps2q[j * 1024 + b];
    }
    __shared__ double rs[256], rq[256];
    rs[tid] = sm; rq[tid] = sq;
    __syncthreads();
    for (int o = 128; o > 0; o >>= 1) {
        if (tid < o) { rs[tid] += rs[tid + o]; rq[tid] += rq[tid + o]; }
        __syncthreads();
    }
    if (tid == 0) {
        double N = 204800.0;
        double mean = rs[0] / N;
        double var = rq[0] / N - mean * mean;
        if (var < 0.0) var = 0.0;
        g_mean2[j] = (float)mean;
        g_istd2[j] = (float)(1.0 / sqrt(var + 1e-9));
    }
}

// ---------------- kernel C: dice1 + mw2 GEMM, pipelined + fused stats-2 epilogue ----------------
constexpr int C_WS = 0;
constexpr int C_XS = 8192;        // two buffers of 6400
constexpr int C_MN = 20992;
constexpr int C_ISD = 21120;
constexpr int C_AL = 21248;
constexpr int C_MB = 21376;
constexpr int SMEM_C_BYTES = 21440 * 4;   // 85760

__global__ void __launch_bounds__(256, 2) kC(
    const float* __restrict__ mw2, const float* __restrict__ mb2,
    const float* __restrict__ alpha1)
{
    extern __shared__ float smc[];
    float* ws  = smc + C_WS;
    float* xs  = smc + C_XS;
    float* mn  = smc + C_MN;
    float* isd = smc + C_ISD;
    float* al  = smc + C_AL;
    float* mbs = smc + C_MB;

    const int tid = threadIdx.x, bh = blockIdx.x;
    const int b = bh >> 2, h = bh & 3;

    for (int i = tid; i < 8192; i += 256) {
        int f = i >> 6, g = i & 63;
        ws[i] = mw2[(size_t)h * 8192 + g * 128 + f];
    }
    if (tid < 128) {
        int j = h * 128 + tid;
        mn[tid] = g_mean1[j]; isd[tid] = g_istd1[j]; al[tid] = alpha1[j];
    } else if (tid < 192) {
        mbs[tid - 128] = mb2[h * 64 + (tid - 128)];
    }
    __syncthreads();   // mn/isd/al ready before dice

    const float* zbase = g_z1 + (size_t)bh * 25600;

    // prologue: stage phase 0 into buffer 0
    #pragma unroll
    for (int k = 0; k < 25; k++) {
        int i = tid + k * 256;
        int f = i / 200;
        float zv = zbase[i];
        float xa = (zv - mn[f]) * isd[f];
        float p = __fdividef(1.f, 1.f + __expf(-xa));
        xs[i] = (p + al[f] * (1.f - p)) * zv;
    }
    __syncthreads();

    const bool act = tid < 200;
    const int t_tile = tid % 50, g_tile = tid / 50;
    const int t0 = t_tile * 4, gb = (g_tile < 4 ? g_tile : 0) * 16;

    u64 acc[4][8];
    #pragma unroll
    for (int t = 0; t < 4; t++)
        #pragma unroll
        for (int p = 0; p < 8; p++) acc[t][p] = 0ull;

    float pre[25];

    for (int ft = 0; ft < 4; ft++) {
        if (ft < 3) {
            const float* zp = zbase + (ft + 1) * 6400;
            #pragma unroll
            for (int k = 0; k < 25; k++) pre[k] = zp[tid + k * 256];
        }
        const float* xcur = xs + (ft & 1) * 6400;
        if (act) {
            #pragma unroll 4
            for (int f = 0; f < 32; f++) {
                float4 xv = *(const float4*)&xcur[f * 200 + t0];
                u64 xt[4];
                xt[0] = pack2(xv.x, xv.x); xt[1] = pack2(xv.y, xv.y);
                xt[2] = pack2(xv.z, xv.z); xt[3] = pack2(xv.w, xv.w);
                const float* wr = &ws[(ft * 32 + f) * 64 + gb];
                u64 wv[8];
                ld2x(wr,      wv[0], wv[1]);
                ld2x(wr + 4,  wv[2], wv[3]);
                ld2x(wr + 8,  wv[4], wv[5]);
                ld2x(wr + 12, wv[6], wv[7]);
                #pragma unroll
                for (int t = 0; t < 4; t++)
                    #pragma unroll
                    for (int p = 0; p < 8; p++)
                        acc[t][p] = fma2(xt[t], wv[p], acc[t][p]);
            }
        }
        if (ft < 3) {
            __syncthreads();
            float* xn = xs + ((ft + 1) & 1) * 6400;
            const int fbase = (ft + 1) * 32;
            #pragma unroll
            for (int k = 0; k < 25; k++) {
                int i = tid + k * 256;
                int fg = fbase + i / 200;
                float zv = pre[k];
                float xa = (zv - mn[fg]) * isd[fg];
                float p = __fdividef(1.f, 1.f + __expf(-xa));
                xn[i] = (p + al[fg] * (1.f - p)) * zv;
            }
            __syncthreads();
        }
    }

    // all ws reads done (last in ft=3 compute) -> reuse ws for stats partials
    __syncthreads();
    float* ps = ws;            // [g*50 + t_tile] per-thread sums
    float* pq = ws + 3200;

    if (act) {
        float* op = g_z2 + (size_t)bh * 12800 + t0;
        #pragma unroll
        for (int p = 0; p < 8; p++) {
            float e0, o0, e1, o1, e2, o2, e3, o3;
            unpack2(acc[0][p], e0, o0); unpack2(acc[1][p], e1, o1);
            unpack2(acc[2][p], e2, o2); unpack2(acc[3][p], e3, o3);
            int ge = gb + 2 * p, go = ge + 1;
            float be = mbs[ge], bo = mbs[go];
            float4 ve = make_float4(e0 + be, e1 + be, e2 + be, e3 + be);
            float4 vo = make_float4(o0 + bo, o1 + bo, o2 + bo, o3 + bo);
            *(float4*)&op[(size_t)ge * 200] = ve;
            *(float4*)&op[(size_t)go * 200] = vo;
            // stats partials (deterministic order)
            ps[ge * 50 + t_tile] = ((ve.x + ve.y) + (ve.z + ve.w));
            pq[ge * 50 + t_tile] = fmaf(ve.x, ve.x, fmaf(ve.y, ve.y, fmaf(ve.z, ve.z, ve.w * ve.w)));
            ps[go * 50 + t_tile] = ((vo.x + vo.y) + (vo.z + vo.w));
            pq[go * 50 + t_tile] = fmaf(vo.x, vo.x, fmaf(vo.y, vo.y, fmaf(vo.z, vo.z, vo.w * vo.w)));
        }
    }
    __syncthreads();

    if (tid < 64) {
        float sm = 0.f, sq = 0.f;
        const float* pr = &ps[tid * 50];
        const float* qr = &pq[tid * 50];
        #pragma unroll 5
        for (int i = 0; i < 50; i++) { sm += pr[i]; sq += qr[i]; }
        int j = h * 64 + tid;
        g_ps2s[j * 1024 + b] = sm;
        g_ps2q[j * 1024 + b] = sq;
    }
}

// ---------------- kernel E: dice2 + score + softmax + pooling ----------------
__global__ void __launch_bounds__(256) kE(
    const int* __restrict__ mask, const float* __restrict__ mw3,
    const float* __restrict__ mb3, const float* __restrict__ alpha2,
    float* __restrict__ out)
{
    __shared__ float w3s[64], m2s[64], i2s[64], a2s[64];
    __shared__ float red[256];
    __shared__ float wts[200];
    const int tid = threadIdx.x, bid = blockIdx.x;
    const int b = bid >> 2, h = bid & 3;
    if (tid < 64) {
        int j = h * 64 + tid;
        w3s[tid] = mw3[j]; m2s[tid] = g_mean2[j]; i2s[tid] = g_istd2[j]; a2s[tid] = alpha2[j];
    }
    __syncthreads();

    float sc = -3.0e38f;
    if (tid < 200) {
        const float* zp = g_z2 + (size_t)bid * 12800 + tid;
        float a = 0.f;
        #pragma unroll 4
        for (int g = 0; g < 64; g++) {
            float zv = zp[g * 200];
            float xa = (zv - m2s[g]) * i2s[g];
            float p = __fdividef(1.f, 1.f + __expf(-xa));
            float xv = (p + a2s[g] * (1.f - p)) * zv;
            a = fmaf(xv, w3s[g], a);
        }
        sc = a + mb3[h];
        if (mask[b * 200 + tid] == 0) sc = -1e9f;
    }
    red[tid] = sc;
    __syncthreads();
    for (int o = 128; o > 0; o >>= 1) {
        if (tid < o) red[tid] = fmaxf(red[tid], red[tid + o]);
        __syncthreads();
    }
    float mx = red[0];
    __syncthreads();
    float e = (tid < 200) ? __expf(sc - mx) : 0.f;
    red[tid] = e;
    __syncthreads();
    for (int o = 128; o > 0; o >>= 1) {
        if (tid < o) red[tid] += red[tid + o];
        __syncthreads();
    }
    float inv = 1.f / red[0];
    if (tid < 200) wts[tid] = e * inv;
    __syncthreads();

    const int c = tid >> 6, d = tid & 63;
    const float* hp = g_ho + (size_t)bid * 12800 + d * 200 + c * 50;
    float acc = 0.f;
    #pragma unroll 2
    for (int i = 0; i < 50; i++)
        acc = fmaf(wts[c * 50 + i], hp[i], acc);
    red[tid] = acc;
    __syncthreads();
    if (tid < 64)
        out[(size_t)bid * 64 + tid] = (red[tid] + red[tid + 64]) + (red[tid + 128] + red[tid + 192]);
}

// ---------------- launch ----------------
extern "C" void kernel_launch(void* const* d_in, const int* in_sizes, int n_in,
                              void* d_out, int out_size)
{
    const float* seq  = (const float*)d_in[0];
    const float* targ = (const float*)d_in[1];
    const int*   mask = (const int*)d_in[2];
    const float* Wqkv = (const float*)d_in[3];
    const float* Wo   = (const float*)d_in[4];
    const float* lng  = (const float*)d_in[5];
    const float* lnb  = (const float*)d_in[6];
    const float* fw1  = (const float*)d_in[7];
    const float* fb1  = (const float*)d_in[8];
    const float* fw2  = (const float*)d_in[9];
    const float* fb2  = (const float*)d_in[10];
    const float* mw1  = (const float*)d_in[11];
    const float* mb1  = (const float*)d_in[12];
    const float* a1   = (const float*)d_in[13];
    const float* mw2  = (const float*)d_in[14];
    const float* mb2  = (const float*)d_in[15];
    const float* a2   = (const float*)d_in[16];
    const float* mw3  = (const float*)d_in[17];
    const float* mb3  = (const float*)d_in[18];
    float* out = (float*)d_out;

    cudaFuncSetAttribute(kA, cudaFuncAttributeMaxDynamicSharedMemorySize, SMEM_A_BYTES);
    cudaFuncSetAttribute(kB, cudaFuncAttributeMaxDynamicSharedMemorySize, SMEM_B_BYTES);
    cudaFuncSetAttribute(kC, cudaFuncAttributeMaxDynamicSharedMemorySize, SMEM_C_BYTES);

    kW<<<64, 256>>>(fw2);
    kB0<<<4096, 128>>>(mw1, mb1, targ);
    kA<<<4096, 256, SMEM_A_BYTES>>>(seq, Wqkv, Wo, lng, lnb, fw1, fb1, fb2);
    kB<<<8192, 256, SMEM_B_BYTES>>>(mw1, targ);
    kP1<<<4096, 256>>>();
    kFin1<<<1, 512>>>();
    kC<<<4096, 256, SMEM_C_BYTES>>>(mw2, mb2, a1);
    kFin2<<<256, 256>>>();
    kE<<<4096, 256>>>(mask, mw3, mb3, a2, out);
}